// round 14
// baseline (speedup 1.0000x reference)
#include <cuda_runtime.h>
#include <cuda_bf16.h>
#include <cuda_fp16.h>
#include <math.h>
#include <stdint.h>

#define TOK   2048      // B*S
#define HID   1024
#define KAUG  9216      // H*(1+NB)
#define NB    8
#define NHEAD 16
#define HDIM  64
#define SEQ   1024
#define BATCH 2
#define DFF   1024
#define NEXP  4

// ---------------- scratch (static device globals; no runtime alloc) ----------------
__device__ __align__(16) __half        g_phiF[(size_t)TOK * KAUG];          // single fp16
__device__ __align__(16) __half        g_phitF[(size_t)NEXP * TOK * KAUG];  // single fp16
__device__ __align__(16) __nv_bfloat16 g_ctxH[(size_t)TOK * HID];
__device__ __align__(16) __nv_bfloat16 g_ctxL[(size_t)TOK * HID];
__device__ __align__(16) __nv_bfloat16 g_owH[(size_t)HID * HID];
__device__ __align__(16) __nv_bfloat16 g_owL[(size_t)HID * HID];
__device__ __align__(16) __half g_qkvF[(size_t)TOK * 3 * HID];

__device__ float g_x2[(size_t)TOK * HID];
__device__ float g_t1[(size_t)NEXP * TOK * DFF];
__device__ float g_t2[(size_t)NEXP * TOK * DFF];
__device__ float g_logits[TOK * NEXP];
__device__ int   g_cnt[NEXP];
__device__ int   g_eidx[NEXP * TOK];
__device__ float g_ew[NEXP * TOK];

// ---------------- helpers ----------------------------------------------------------
__device__ __forceinline__ uint32_t smem_u32(const void* p) {
    uint32_t a;
    asm("{ .reg .u64 t; cvta.to.shared.u64 t, %1; cvt.u32.u64 %0, t; }" : "=r"(a) : "l"(p));
    return a;
}

__device__ __forceinline__ void hl_pair(float v, __nv_bfloat16& h, __nv_bfloat16& l) {
    h = __float2bfloat16_rn(v);
    l = __float2bfloat16_rn(v - __bfloat162float(h));
}

template <int ISF16>
__device__ __forceinline__ void mma_any(float* c, uint32_t a0, uint32_t a1, uint32_t a2,
                                        uint32_t a3, uint32_t b0, uint32_t b1) {
    if (ISF16) {
        asm volatile(
            "mma.sync.aligned.m16n8k16.row.col.f32.f16.f16.f32 "
            "{%0,%1,%2,%3}, {%4,%5,%6,%7}, {%8,%9}, {%0,%1,%2,%3};\n"
            : "+f"(c[0]), "+f"(c[1]), "+f"(c[2]), "+f"(c[3])
            : "r"(a0), "r"(a1), "r"(a2), "r"(a3), "r"(b0), "r"(b1));
    } else {
        asm volatile(
            "mma.sync.aligned.m16n8k16.row.col.f32.bf16.bf16.f32 "
            "{%0,%1,%2,%3}, {%4,%5,%6,%7}, {%8,%9}, {%0,%1,%2,%3};\n"
            : "+f"(c[0]), "+f"(c[1]), "+f"(c[2]), "+f"(c[3])
            : "r"(a0), "r"(a1), "r"(a2), "r"(a3), "r"(b0), "r"(b1));
    }
}

#define LDSM_X4(r0, r1, r2, r3, addr) \
    asm volatile("ldmatrix.sync.aligned.m8n8.x4.shared.b16 {%0,%1,%2,%3}, [%4];" \
                 : "=r"(r0), "=r"(r1), "=r"(r2), "=r"(r3) : "r"(addr))

// ---------------- cubic B-spline bases --------------------------------------------
__device__ __forceinline__ void bspline8(float v, float* out) {
    float b[11];
#pragma unroll
    for (int t = 0; t < 11; t++) {
        float g0 = 0.4f * (t - 3) - 1.0f;
        float g1 = 0.4f * (t - 2) - 1.0f;
        b[t] = (v >= g0 && v < g1) ? 1.0f : 0.0f;
    }
#pragma unroll
    for (int j = 1; j <= 3; j++) {
        float inv = 1.0f / (0.4f * (float)j);
#pragma unroll
        for (int t = 0; t < 10; t++) {
            if (t < 11 - j) {
                float gt   = 0.4f * (t - 3) - 1.0f;
                float gtj1 = 0.4f * (t + j - 2) - 1.0f;
                b[t] = (v - gt) * inv * b[t] + (gtj1 - v) * inv * b[t + 1];
            }
        }
    }
#pragma unroll
    for (int c = 0; c < 8; c++) out[c] = b[c];
}

// ---------------- out_w conversion (bf16 hi/lo, small) -----------------------------
__global__ void conv_plain(const float* __restrict__ W,
                           __nv_bfloat16* __restrict__ WH, __nv_bfloat16* __restrict__ WL,
                           int total) {
    int i = blockIdx.x * 256 + threadIdx.x;
    if (i < total) {
        __nv_bfloat16 h, l;
        hl_pair(W[i], h, l);
        WH[i] = h; WL[i] = l;
    }
}

// ---------------- rmsnorm + phi (single fp16) + optional gate logits ---------------
__global__ void rmsnorm_phi_kernel(const float* __restrict__ x,
                                   const float* __restrict__ w,
                                   __half* __restrict__ phiF,
                                   const float* __restrict__ gate_w,
                                   float* __restrict__ logits) {
    int m = blockIdx.x;
    int tid = threadIdx.x;
    __shared__ float sx[HID];
    __shared__ float sred[256];
    const float* xr = x + (size_t)m * HID;
    float ss = 0.f;
    for (int f = tid; f < HID; f += 256) { float v = xr[f]; sx[f] = v; ss += v * v; }
    sred[tid] = ss; __syncthreads();
    for (int o = 128; o > 0; o >>= 1) { if (tid < o) sred[tid] += sred[tid + o]; __syncthreads(); }
    float rms = rsqrtf(sred[0] / (float)HID + 1e-6f);
    float gacc[4] = {0.f, 0.f, 0.f, 0.f};
    __half* ph = phiF + (size_t)m * KAUG;
    for (int f = tid; f < HID; f += 256) {
        float hn = sx[f] * rms * w[f];
        ph[f] = __float2half_rn(hn / (1.0f + expf(-hn)));
        float bs[8];
        bspline8(hn, bs);
#pragma unroll
        for (int c = 0; c < 8; c++)
            ph[HID + f * 8 + c] = __float2half_rn(bs[c]);
        if (gate_w) {
#pragma unroll
            for (int e = 0; e < 4; e++) gacc[e] += hn * gate_w[e * HID + f];
        }
    }
    if (gate_w) {
#pragma unroll
        for (int e = 0; e < 4; e++) {
            __syncthreads();
            sred[tid] = gacc[e]; __syncthreads();
            for (int o = 128; o > 0; o >>= 1) { if (tid < o) sred[tid] += sred[tid + o]; __syncthreads(); }
            if (tid == 0) logits[m * 4 + e] = sred[0];
        }
    }
}

// ---------------- phi expansion of t1*t2, batched over experts (single fp16) -------
__global__ void mul_phi_kernel() {
    int e = blockIdx.y;
    int r = blockIdx.x;
    if (r >= g_cnt[e]) return;
    int tid = threadIdx.x;
    const float* a = g_t1 + (size_t)e * TOK * DFF + (size_t)r * DFF;
    const float* b = g_t2 + (size_t)e * TOK * DFF + (size_t)r * DFF;
    __half* ph = g_phitF + (size_t)e * TOK * KAUG + (size_t)r * KAUG;
    for (int f = tid; f < DFF; f += 256) {
        float v = a[f] * b[f];
        ph[f] = __float2half_rn(v / (1.0f + expf(-v)));
        float bs[8];
        bspline8(v, bs);
#pragma unroll
        for (int c = 0; c < 8; c++)
            ph[DFF + f * 8 + c] = __float2half_rn(bs[c]);
    }
}

// ---------------- tensor-core GEMM body --------------------------------------------
// PASSES=3 (CVTB=0): tiles AH AL BH BL bf16 hi/lo split (precision anchor).
// PASSES=1, CVTB=1: A fp16 via cp.async; B converted INLINE from fp32 KAN weights
//                   (base | spline*scaler), software-pipelined in registers.
// EPI 0: plain fp32. EPI 1: +res+bias dual store. EPI 3: atomic scatter.
// EPI 4: RoPE then fp16 store (C reinterpreted as __half*).
#define PITCH  80
#define TILEB  (128 * PITCH)
#define GM_DYN3 (512 + 2 * 4 * TILEB)
#define GM_DYN1 (512 + 2 * 2 * TILEB)

template <int EPI, int PASSES, int ISF16, int CVTB>
__device__ __forceinline__ void gemm_body(
    const uint16_t* __restrict__ AH, const uint16_t* __restrict__ AL,
    int lda, const int* __restrict__ a_idx,
    const uint16_t* __restrict__ BH, const uint16_t* __restrict__ BL, int ldb,
    const float* __restrict__ Bb, const float* __restrict__ Bsp,
    const float* __restrict__ Bsc, int Kin,
    float* __restrict__ C, int ldc, int M, int K,
    const int* __restrict__ cnt,
    const float* __restrict__ aux0, const float* __restrict__ aux1, float* __restrict__ C2,
    const int* __restrict__ out_idx, const float* __restrict__ out_wt) {
    const int NT = (PASSES == 3) ? 4 : 2;
    const int BT = (PASSES == 3) ? 2 : 1;
    const uint32_t STAGEB = (uint32_t)NT * TILEB;

    int Meff = cnt ? *cnt : M;
    int mBase = blockIdx.y * 128;
    int nBase = blockIdx.x * 128;
    if (mBase >= Meff) return;

    extern __shared__ char sm[];
    int* rowmap = (int*)sm;
    uint32_t bufs_u = smem_u32(sm + 512);
    int tid = threadIdx.x;

    if (tid < 128) {
        int r = mBase + tid;
        int g = (r < Meff) ? r : mBase;
        rowmap[tid] = a_idx ? a_idx[g] : g;
    }
    __syncthreads();

    int w = tid >> 5, l = tid & 31;
    int wm = (w >> 2) * 64;
    int wn = (w & 3) * 32;
    int lq = l >> 2, lr = l & 3;
    uint32_t aOff = (uint32_t)(wm + (l & 15)) * PITCH + ((l >> 4) ? 16u : 0u);
    uint32_t bOff = (uint32_t)(wn + (l & 7) + ((l & 16) ? 8 : 0)) * PITCH + ((l & 8) ? 16u : 0u);

    // inline B conversion assignment
    int brow = tid >> 1;
    int bkh = (tid & 1) * 16;
    const float* Bb_row = CVTB ? Bb + (size_t)(nBase + brow) * Kin : nullptr;
    const float* Bs_row = CVTB ? Bsp + (size_t)(nBase + brow) * (Kin * 8) : nullptr;
    const float* Bc_row = CVTB ? Bsc + (size_t)(nBase + brow) * Kin : nullptr;

    float acc[4][4][4];
#pragma unroll
    for (int mf = 0; mf < 4; mf++)
#pragma unroll
        for (int nf = 0; nf < 4; nf++)
#pragma unroll
            for (int t = 0; t < 4; t++) acc[mf][nf][t] = 0.f;

    float bf[16];
    auto load_breg = [&](int k0) {
        int kg = k0 + bkh;
        if (kg < Kin) {
#pragma unroll
            for (int u = 0; u < 4; u++)
                *(float4*)(bf + 4 * u) = *(const float4*)(Bb_row + kg + 4 * u);
        } else {
            int ko = kg - Kin;
#pragma unroll
            for (int u = 0; u < 4; u++)
                *(float4*)(bf + 4 * u) = *(const float4*)(Bs_row + ko + 4 * u);
            float sc0 = Bc_row[ko >> 3];
            float sc1 = Bc_row[(ko + 8) >> 3];
#pragma unroll
            for (int u = 0; u < 8; u++) bf[u] *= sc0;
#pragma unroll
            for (int u = 8; u < 16; u++) bf[u] *= sc1;
        }
    };
    auto store_breg = [&](int s) {
        char* dst = sm + 512 + (size_t)s * STAGEB + TILEB + brow * PITCH + (bkh ? 32 : 0);
        __half2 h[8];
#pragma unroll
        for (int u = 0; u < 8; u++) h[u] = __floats2half2_rn(bf[2 * u], bf[2 * u + 1]);
        *(uint4*)(dst) = *(uint4*)(h);
        *(uint4*)(dst + 16) = *(uint4*)(h + 4);
    };

    auto issue = [&](int s, int k0) {
        const int CPIT = (PASSES == 3) ? 8 : (CVTB ? 2 : 4);
#pragma unroll
        for (int it = 0; it < CPIT; it++) {
            int i = it * 256 + tid;
            int tens = i >> 9;
            int rem = i & 511;
            int row = rem >> 2;
            int seg = rem & 3;
            const uint16_t* src;
            if (PASSES == 1) {
                src = (tens == 0) ? AH + (size_t)rowmap[row] * lda + k0 + 8 * seg
                                  : BH + (size_t)(nBase + row) * ldb + k0 + 8 * seg;
            } else {
                if (tens == 0)      src = AH + (size_t)rowmap[row] * lda + k0 + 8 * seg;
                else if (tens == 1) src = AL + (size_t)rowmap[row] * lda + k0 + 8 * seg;
                else if (tens == 2) src = BH + (size_t)(nBase + row) * ldb + k0 + 8 * seg;
                else                src = BL + (size_t)(nBase + row) * ldb + k0 + 8 * seg;
            }
            uint32_t dst = bufs_u + (uint32_t)s * STAGEB + (uint32_t)tens * TILEB +
                           (uint32_t)row * PITCH + (uint32_t)seg * 16;
            asm volatile("cp.async.cg.shared.global [%0], [%1], 16;" :: "r"(dst), "l"(src) : "memory");
        }
        asm volatile("cp.async.commit_group;" ::: "memory");
    };

    int nStages = K / 32;
    if (CVTB) load_breg(0);
    issue(0, 0);
    for (int ck = 0; ck < nStages; ck++) {
        bool pre = (ck + 1 < nStages);
        if (pre) issue((ck + 1) & 1, (ck + 1) * 32);
        if (CVTB) {
            store_breg(ck & 1);
            if (pre) load_breg((ck + 1) * 32);
        }
        if (pre) asm volatile("cp.async.wait_group 1;" ::: "memory");
        else     asm volatile("cp.async.wait_group 0;" ::: "memory");
        __syncthreads();

        uint32_t base = bufs_u + (uint32_t)(ck & 1) * STAGEB;
#pragma unroll
        for (int p = 0; p < 2; p++) {
            uint32_t koff = 32u * p;
            if (PASSES == 3) {
                uint32_t bH[4][2], bL[4][2], af[4][4];
#pragma unroll
                for (int nh = 0; nh < 2; nh++) {
                    uint32_t r0, r1, r2, r3;
                    LDSM_X4(r0, r1, r2, r3, base + 2 * TILEB + bOff + nh * 16 * PITCH + koff);
                    bH[2 * nh][0] = r0; bH[2 * nh][1] = r1; bH[2 * nh + 1][0] = r2; bH[2 * nh + 1][1] = r3;
                    LDSM_X4(r0, r1, r2, r3, base + 3 * TILEB + bOff + nh * 16 * PITCH + koff);
                    bL[2 * nh][0] = r0; bL[2 * nh][1] = r1; bL[2 * nh + 1][0] = r2; bL[2 * nh + 1][1] = r3;
                }
#pragma unroll
                for (int mf = 0; mf < 4; mf++)
                    LDSM_X4(af[mf][0], af[mf][1], af[mf][2], af[mf][3],
                            base + 0 * TILEB + aOff + mf * 16 * PITCH + koff);
#pragma unroll
                for (int mf = 0; mf < 4; mf++)
#pragma unroll
                    for (int nf = 0; nf < 4; nf++)
                        mma_any<ISF16>(acc[mf][nf], af[mf][0], af[mf][1], af[mf][2], af[mf][3],
                                       bH[nf][0], bH[nf][1]);
#pragma unroll
                for (int mf = 0; mf < 4; mf++)
#pragma unroll
                    for (int nf = 0; nf < 4; nf++)
                        mma_any<ISF16>(acc[mf][nf], af[mf][0], af[mf][1], af[mf][2], af[mf][3],
                                       bL[nf][0], bL[nf][1]);
#pragma unroll
                for (int mf = 0; mf < 4; mf++)
                    LDSM_X4(af[mf][0], af[mf][1], af[mf][2], af[mf][3],
                            base + 1 * TILEB + aOff + mf * 16 * PITCH + koff);
#pragma unroll
                for (int mf = 0; mf < 4; mf++)
#pragma unroll
                    for (int nf = 0; nf < 4; nf++)
                        mma_any<ISF16>(acc[mf][nf], af[mf][0], af[mf][1], af[mf][2], af[mf][3],
                                       bH[nf][0], bH[nf][1]);
            } else {
                uint32_t bb[4][2], af[4][4];
#pragma unroll
                for (int nh = 0; nh < 2; nh++) {
                    uint32_t r0, r1, r2, r3;
                    LDSM_X4(r0, r1, r2, r3, base + BT * TILEB + bOff + nh * 16 * PITCH + koff);
                    bb[2 * nh][0] = r0; bb[2 * nh][1] = r1; bb[2 * nh + 1][0] = r2; bb[2 * nh + 1][1] = r3;
                }
#pragma unroll
                for (int mf = 0; mf < 4; mf++)
                    LDSM_X4(af[mf][0], af[mf][1], af[mf][2], af[mf][3],
                            base + 0 * TILEB + aOff + mf * 16 * PITCH + koff);
#pragma unroll
                for (int mf = 0; mf < 4; mf++)
#pragma unroll
                    for (int nf = 0; nf < 4; nf++)
                        mma_any<ISF16>(acc[mf][nf], af[mf][0], af[mf][1], af[mf][2], af[mf][3],
                                       bb[nf][0], bb[nf][1]);
            }
        }
        __syncthreads();
    }

    // ---- epilogue ----
#pragma unroll
    for (int mf = 0; mf < 4; mf++) {
#pragma unroll
        for (int nf = 0; nf < 4; nf++) {
            float* c = acc[mf][nf];
            int r0 = mBase + wm + mf * 16 + lq;
            int c0 = nBase + wn + nf * 8 + 2 * lr;
#pragma unroll
            for (int half = 0; half < 2; half++) {
                int r = r0 + half * 8;
                if (r >= Meff) continue;
                float v0 = c[half * 2 + 0], v1 = c[half * 2 + 1];
                if (EPI == 0) {
                    C[(size_t)r * ldc + c0] = v0;
                    C[(size_t)r * ldc + c0 + 1] = v1;
                } else if (EPI == 1) {
                    float o0 = v0 + aux0[(size_t)r * ldc + c0] + aux1[c0];
                    float o1 = v1 + aux0[(size_t)r * ldc + c0 + 1] + aux1[c0 + 1];
                    C[(size_t)r * ldc + c0] = o0;  C2[(size_t)r * ldc + c0] = o0;
                    C[(size_t)r * ldc + c0 + 1] = o1; C2[(size_t)r * ldc + c0 + 1] = o1;
                } else if (EPI == 3) {
                    int tok = out_idx[r];
                    float wgt = out_wt[r];
                    atomicAdd(&C[(size_t)tok * ldc + c0], wgt * v0);
                    atomicAdd(&C[(size_t)tok * ldc + c0 + 1], wgt * v1);
                } else {   // EPI == 4: RoPE on q,k pairs then fp16 store
                    __half* Ch = (__half*)C;
                    int s = r & (SEQ - 1);
                    int sub = c0 % 192;
                    float o0, o1;
                    if (sub < 128) {
                        int d2 = (sub & 63) >> 1;
                        float cc = aux0[s * 32 + d2], sn = aux1[s * 32 + d2];
                        o0 = v0 * cc - v1 * sn;
                        o1 = v0 * sn + v1 * cc;
                    } else {
                        o0 = v0; o1 = v1;
                    }
                    *(__half2*)(Ch + (size_t)r * ldc + c0) = __floats2half2_rn(o0, o1);
                }
            }
        }
    }
}

// QKV: fp16 1-pass, inline weight conversion, fused RoPE, fp16 output
__global__ void __launch_bounds__(256, 2)
kan_gemm_qkv(const float* __restrict__ rc, const float* __restrict__ rs,
             const float* __restrict__ wb, const float* __restrict__ wsp,
             const float* __restrict__ wsc) {
    gemm_body<4, 1, 1, 1>((const uint16_t*)g_phiF, nullptr, KAUG, nullptr,
                          nullptr, nullptr, 0, wb, wsp, wsc, HID,
                          (float*)g_qkvF, 3072, TOK, KAUG, nullptr, rc, rs, nullptr,
                          nullptr, nullptr);
}

// out-proj: bf16 3-pass, residual+bias dual store (precision anchor)
__global__ void __launch_bounds__(256, 2)
kan_gemm_op(const float* __restrict__ x, const float* __restrict__ bias,
            float* __restrict__ x2, float* __restrict__ out) {
    gemm_body<1, 3, 0, 0>((const uint16_t*)g_ctxH, (const uint16_t*)g_ctxL, HID, nullptr,
                          (const uint16_t*)g_owH, (const uint16_t*)g_owL, HID,
                          nullptr, nullptr, nullptr, 0,
                          x2, HID, TOK, HID, nullptr, x, bias, out, nullptr, nullptr);
}

// batched w1+w2: fp16 1-pass, inline weight conversion
__global__ void __launch_bounds__(256, 2)
kan_gemm_w12(const float* __restrict__ w1b, const float* __restrict__ w1sp,
             const float* __restrict__ w1sc,
             const float* __restrict__ w2b, const float* __restrict__ w2sp,
             const float* __restrict__ w2sc) {
    int z = blockIdx.z, e = z >> 1, sel = z & 1;
    const float* wb  = (sel ? w2b  : w1b)  + (size_t)e * DFF * HID;
    const float* wsp = (sel ? w2sp : w1sp) + (size_t)e * DFF * HID * 8;
    const float* wsc = (sel ? w2sc : w1sc) + (size_t)e * DFF * HID;
    float* C = (sel ? g_t2 : g_t1) + (size_t)e * TOK * DFF;
    gemm_body<0, 1, 1, 1>((const uint16_t*)g_phiF, nullptr, KAUG,
                          g_eidx + e * TOK, nullptr, nullptr, 0, wb, wsp, wsc, HID,
                          C, DFF, TOK, KAUG, g_cnt + e, nullptr, nullptr, nullptr,
                          nullptr, nullptr);
}

// batched w3: fp16 1-pass, inline weight conversion, atomic scatter
__global__ void __launch_bounds__(256, 2)
kan_gemm_w3(float* __restrict__ out,
            const float* __restrict__ w3b, const float* __restrict__ w3sp,
            const float* __restrict__ w3sc) {
    int e = blockIdx.z;
    gemm_body<3, 1, 1, 1>((const uint16_t*)(g_phitF + (size_t)e * TOK * KAUG), nullptr,
                          KAUG, nullptr, nullptr, nullptr, 0,
                          w3b + (size_t)e * HID * DFF,
                          w3sp + (size_t)e * HID * DFF * 8,
                          w3sc + (size_t)e * HID * DFF, DFF,
                          out, HID, TOK, KAUG, g_cnt + e, nullptr, nullptr, nullptr,
                          g_eidx + e * TOK, g_ew + e * TOK);
}

// ---------------- FlashAttention-2 on tensor cores (fp16 qkv input) ----------------
#define FAQ   128
#define FAP   72
__global__ void __launch_bounds__(256, 1)
flash_attn_kernel(const __half* __restrict__ qkv,
                  __nv_bfloat16* __restrict__ ctxH,
                  __nv_bfloat16* __restrict__ ctxL) {
    __shared__ __half Qs[FAQ * FAP];
    __shared__ __half Ks[64 * FAP];
    __shared__ __half Vs[64 * FAP];

    int qt = blockIdx.x, bh = blockIdx.y;
    int b = bh >> 4, h = bh & 15;
    int tid = threadIdx.x;
    int w = tid >> 5, l = tid & 31;
    int lq = l >> 2, lr = l & 3;
    uint32_t qs_u = smem_u32(Qs), ks_u = smem_u32(Ks), vs_u = smem_u32(Vs);

    // ---- load Q tile (pure fp16 copy) ----
    {
        int row = tid >> 1;
        int cb = (tid & 1) * 32;
        const uint4* src = (const uint4*)(qkv + (size_t)(b * SEQ + qt * FAQ + row) * 3072 +
                                          h * 192 + cb);
        uint4* dst = (uint4*)(Qs + row * FAP + cb);
#pragma unroll
        for (int u = 0; u < 4; u++) dst[u] = src[u];
    }

    float o[8][4];
#pragma unroll
    for (int t = 0; t < 8; t++)
#pragma unroll
        for (int j = 0; j < 4; j++) o[t][j] = 0.f;
    float m0 = -1e30f, m1 = -1e30f, l0 = 0.f, l1 = 0.f;

    for (int kt = 0; kt < SEQ / 64; kt++) {
        __syncthreads();
        {
            int row = tid >> 2;
            int cb = (tid & 3) * 16;
            const __half* ks = qkv + (size_t)(b * SEQ + kt * 64 + row) * 3072 + h * 192 + 64 + cb;
            const __half* vsp = ks + 64;
            uint4* kd = (uint4*)(Ks + row * FAP + cb);
            kd[0] = *(const uint4*)(ks);
            kd[1] = *(const uint4*)(ks + 8);
            uint4 vv0 = *(const uint4*)(vsp);
            uint4 vv1 = *(const uint4*)(vsp + 8);
            const __half* vh0 = (const __half*)&vv0;
            const __half* vh1 = (const __half*)&vv1;
#pragma unroll
            for (int j = 0; j < 8; j++) {
                Vs[(cb + j) * FAP + row] = vh0[j];
                Vs[(cb + 8 + j) * FAP + row] = vh1[j];
            }
        }
        __syncthreads();

        // ---- S = Q K^T ----
        float s[8][4];
#pragma unroll
        for (int t = 0; t < 8; t++)
#pragma unroll
            for (int j = 0; j < 4; j++) s[t][j] = 0.f;
#pragma unroll
        for (int kk = 0; kk < 4; kk++) {
            uint32_t a0, a1, a2, a3;
            LDSM_X4(a0, a1, a2, a3,
                    qs_u + ((w * 16 + (l & 15)) * FAP + (l >> 4) * 8 + kk * 16) * 2);
#pragma unroll
            for (int jp = 0; jp < 4; jp++) {
                uint32_t r0, r1, r2, r3;
                LDSM_X4(r0, r1, r2, r3,
                        ks_u + ((jp * 16 + (l & 7) + ((l & 16) ? 8 : 0)) * FAP + kk * 16) * 2 +
                        ((l & 8) ? 16u : 0u));
                mma_any<1>(s[2 * jp],     a0, a1, a2, a3, r0, r1);
                mma_any<1>(s[2 * jp + 1], a0, a1, a2, a3, r2, r3);
            }
        }

        // ---- softmax update ----
        float mx0 = m0, mx1 = m1;
#pragma unroll
        for (int t = 0; t < 8; t++) {
#pragma unroll
            for (int j = 0; j < 4; j++) s[t][j] *= 0.125f;
            mx0 = fmaxf(mx0, fmaxf(s[t][0], s[t][1]));
            mx1 = fmaxf(mx1, fmaxf(s[t][2], s[t][3]));
        }
        mx0 = fmaxf(mx0, __shfl_xor_sync(0xffffffff, mx0, 1));
        mx0 = fmaxf(mx0, __shfl_xor_sync(0xffffffff, mx0, 2));
        mx1 = fmaxf(mx1, __shfl_xor_sync(0xffffffff, mx1, 1));
        mx1 = fmaxf(mx1, __shfl_xor_sync(0xffffffff, mx1, 2));
        float corr0 = __expf(m0 - mx0), corr1 = __expf(m1 - mx1);
        m0 = mx0; m1 = mx1;

        uint32_t ph[8], pl[8];
        float sum0 = 0.f, sum1 = 0.f;
#pragma unroll
        for (int t = 0; t < 8; t++) {
            float p0 = __expf(s[t][0] - mx0);
            float p1 = __expf(s[t][1] - mx0);
            float p2 = __expf(s[t][2] - mx1);
            float p3 = __expf(s[t][3] - mx1);
            sum0 += p0 + p1; sum1 += p2 + p3;
            __half2 h0 = __floats2half2_rn(p0, p1);
            __half2 h1 = __floats2half2_rn(p2, p3);
            ph[t] = *reinterpret_cast<uint32_t*>(&h0);
            pl[t] = *reinterpret_cast<uint32_t*>(&h1);
        }
        sum0 += __shfl_xor_sync(0xffffffff, sum0, 1);
        sum0 += __shfl_xor_sync(0xffffffff, sum0, 2);
        sum1 += __shfl_xor_sync(0xffffffff, sum1, 1);
        sum1 += __shfl_xor_sync(0xffffffff, sum1, 2);
        l0 = corr0 * l0 + sum0;
        l1 = corr1 * l1 + sum1;
#pragma unroll
        for (int t = 0; t < 8; t++) {
            o[t][0] *= corr0; o[t][1] *= corr0;
            o[t][2] *= corr1; o[t][3] *= corr1;
        }

        // ---- O += P V ----
#pragma unroll
        for (int kk = 0; kk < 4; kk++) {
            uint32_t a0 = ph[2 * kk], a1 = pl[2 * kk];
            uint32_t a2 = ph[2 * kk + 1], a3 = pl[2 * kk + 1];
#pragma unroll
            for (int jp = 0; jp < 4; jp++) {
                uint32_t r0, r1, r2, r3;
                LDSM_X4(r0, r1, r2, r3,
                        vs_u + ((jp * 16 + (l & 7) + ((l & 16) ? 8 : 0)) * FAP + kk * 16) * 2 +
                        ((l & 8) ? 16u : 0u));
                mma_any<1>(o[2 * jp],     a0, a1, a2, a3, r0, r1);
                mma_any<1>(o[2 * jp + 1], a0, a1, a2, a3, r2, r3);
            }
        }
    }

    // ---- normalize + store ctx as bf16 hi/lo ----
    float inv0 = 1.0f / l0, inv1 = 1.0f / l1;
    int r0g = b * SEQ + qt * FAQ + w * 16 + lq;
#pragma unroll
    for (int t = 0; t < 8; t++) {
        int col = h * 64 + t * 8 + 2 * lr;
        __nv_bfloat16 hh, ll;
        size_t off0 = (size_t)r0g * HID + col;
        size_t off1 = (size_t)(r0g + 8) * HID + col;
        hl_pair(o[t][0] * inv0, hh, ll); ctxH[off0] = hh;     ctxL[off0] = ll;
        hl_pair(o[t][1] * inv0, hh, ll); ctxH[off0 + 1] = hh; ctxL[off0 + 1] = ll;
        hl_pair(o[t][2] * inv1, hh, ll); ctxH[off1] = hh;     ctxL[off1] = ll;
        hl_pair(o[t][3] * inv1, hh, ll); ctxH[off1 + 1] = hh; ctxL[off1 + 1] = ll;
    }
}

// ---------------- MoE routing -----------------------------------------------------
__global__ void init_cnt_kernel() {
    if (threadIdx.x < NEXP) g_cnt[threadIdx.x] = 0;
}

__global__ void routing_kernel() {
    int m = blockIdx.x * 256 + threadIdx.x;
    if (m >= TOK) return;
    float l[4];
#pragma unroll
    for (int e = 0; e < 4; e++) l[e] = g_logits[m * 4 + e];
    int i0 = 0; float b0 = l[0];
#pragma unroll
    for (int e = 1; e < 4; e++) if (l[e] > b0) { b0 = l[e]; i0 = e; }
    int i1 = -1; float b1 = -1e30f;
#pragma unroll
    for (int e = 0; e < 4; e++) if (e != i0 && l[e] > b1) { b1 = l[e]; i1 = e; }
    float t = expf(b1 - b0);
    float w0 = 1.0f / (1.0f + t);
    float w1 = t / (1.0f + t);
    int p0 = atomicAdd(&g_cnt[i0], 1);
    g_eidx[i0 * TOK + p0] = m; g_ew[i0 * TOK + p0] = w0;
    int p1 = atomicAdd(&g_cnt[i1], 1);
    g_eidx[i1 * TOK + p1] = m; g_ew[i1 * TOK + p1] = w1;
}

// ---------------- host orchestration ----------------------------------------------
extern "C" void kernel_launch(void* const* d_in, const int* in_sizes, int n_in,
                              void* d_out, int out_size) {
    const float* x          = (const float*)d_in[0];
    const float* rot_cos    = (const float*)d_in[1];
    const float* rot_sin    = (const float*)d_in[2];
    const float* norm1_w    = (const float*)d_in[3];
    const float* norm2_w    = (const float*)d_in[4];
    const float* qkv_base   = (const float*)d_in[5];
    const float* qkv_spline = (const float*)d_in[6];
    const float* qkv_scaler = (const float*)d_in[7];
    const float* out_w      = (const float*)d_in[8];
    const float* out_b      = (const float*)d_in[9];
    const float* gate_w     = (const float*)d_in[10];
    const float* w1_base    = (const float*)d_in[11];
    const float* w1_spline  = (const float*)d_in[12];
    const float* w1_scaler  = (const float*)d_in[13];
    const float* w2_base    = (const float*)d_in[14];
    const float* w2_spline  = (const float*)d_in[15];
    const float* w2_scaler  = (const float*)d_in[16];
    const float* w3_base    = (const float*)d_in[17];
    const float* w3_spline  = (const float*)d_in[18];
    const float* w3_scaler  = (const float*)d_in[19];
    float* out = (float*)d_out;

    __half *phiF, *qkvF;
    __nv_bfloat16 *ctxH, *ctxL, *owH, *owL;
    float *x2, *logits;
    cudaGetSymbolAddress((void**)&phiF, g_phiF);
    cudaGetSymbolAddress((void**)&qkvF, g_qkvF);
    cudaGetSymbolAddress((void**)&ctxH, g_ctxH);   cudaGetSymbolAddress((void**)&ctxL, g_ctxL);
    cudaGetSymbolAddress((void**)&owH, g_owH);     cudaGetSymbolAddress((void**)&owL, g_owL);
    cudaGetSymbolAddress((void**)&x2, g_x2);
    cudaGetSymbolAddress((void**)&logits, g_logits);

    cudaFuncSetAttribute(kan_gemm_qkv, cudaFuncAttributeMaxDynamicSharedMemorySize, GM_DYN1);
    cudaFuncSetAttribute(kan_gemm_op,  cudaFuncAttributeMaxDynamicSharedMemorySize, GM_DYN3);
    cudaFuncSetAttribute(kan_gemm_w12, cudaFuncAttributeMaxDynamicSharedMemorySize, GM_DYN1);
    cudaFuncSetAttribute(kan_gemm_w3,  cudaFuncAttributeMaxDynamicSharedMemorySize, GM_DYN1);

    // 0) out_w conversion only (KAN weights converted inline in GEMMs)
    conv_plain<<<(HID * HID + 255) / 256, 256>>>(out_w, owH, owL, HID * HID);

    // 1) rmsnorm(x) -> phi fp16
    rmsnorm_phi_kernel<<<TOK, 256>>>(x, norm1_w, phiF, nullptr, nullptr);

    // 2) QKV = phi @ Waug^T (inline conversion, fused RoPE, fp16 out)
    kan_gemm_qkv<<<dim3(3072 / 128, TOK / 128), 256, GM_DYN1>>>(
        rot_cos, rot_sin, qkv_base, qkv_spline, qkv_scaler);

    // 3) attention (FA2 on tensor cores)
    flash_attn_kernel<<<dim3(SEQ / FAQ, BATCH * NHEAD), 256>>>(qkvF, ctxH, ctxL);

    // 4) x2 = x + ctx @ out_w^T + out_b (dual store into d_out)
    kan_gemm_op<<<dim3(HID / 128, TOK / 128), 256, GM_DYN3>>>(x, out_b, x2, out);

    // 5) rmsnorm(x2) -> phi fp16, gate logits
    rmsnorm_phi_kernel<<<TOK, 256>>>(x2, norm2_w, phiF, gate_w, logits);

    // 6) routing
    init_cnt_kernel<<<1, 32>>>();
    routing_kernel<<<TOK / 256, 256>>>();

    // 7) MoE batched (inline conversion)
    kan_gemm_w12<<<dim3(DFF / 128, TOK / 128, 2 * NEXP), 256, GM_DYN1>>>(
        w1_base, w1_spline, w1_scaler, w2_base, w2_spline, w2_scaler);
    mul_phi_kernel<<<dim3(TOK, NEXP), 256>>>();
    kan_gemm_w3<<<dim3(HID / 128, TOK / 128, NEXP), 256, GM_DYN1>>>(
        out, w3_base, w3_spline, w3_scaler);
}

// round 15
// speedup vs baseline: 1.7233x; 1.7233x over previous
#include <cuda_runtime.h>
#include <cuda_bf16.h>
#include <cuda_fp16.h>
#include <math.h>
#include <stdint.h>

#define TOK   2048      // B*S
#define HID   1024
#define KAUG  9216      // H*(1+NB)
#define NB    8
#define NHEAD 16
#define HDIM  64
#define SEQ   1024
#define BATCH 2
#define DFF   1024
#define NEXP  4

// ---------------- scratch (static device globals; no runtime alloc) ----------------
__device__ __align__(16) __half        g_phiF[(size_t)TOK * KAUG];          // single fp16
__device__ __align__(16) __half        g_phitF[(size_t)NEXP * TOK * KAUG];  // single fp16
__device__ __align__(16) __nv_bfloat16 g_ctxH[(size_t)TOK * HID];
__device__ __align__(16) __nv_bfloat16 g_ctxL[(size_t)TOK * HID];
__device__ __align__(16) __half        g_qkvwF[(size_t)3072 * KAUG];
__device__ __align__(16) __half        g_w1F[(size_t)NEXP * DFF * KAUG];
__device__ __align__(16) __half        g_w2F[(size_t)NEXP * DFF * KAUG];
__device__ __align__(16) __half        g_w3F[(size_t)NEXP * HID * KAUG];
__device__ __align__(16) __nv_bfloat16 g_owH[(size_t)HID * HID];
__device__ __align__(16) __nv_bfloat16 g_owL[(size_t)HID * HID];
__device__ __align__(16) __half        g_qkvF[(size_t)TOK * 3 * HID];

__device__ float g_x2[(size_t)TOK * HID];
__device__ float g_t1[(size_t)NEXP * TOK * DFF];
__device__ float g_t2[(size_t)NEXP * TOK * DFF];
__device__ float g_logits[TOK * NEXP];
__device__ int   g_cnt[NEXP];
__device__ int   g_eidx[NEXP * TOK];
__device__ float g_ew[NEXP * TOK];

// ---------------- helpers ----------------------------------------------------------
__device__ __forceinline__ uint32_t smem_u32(const void* p) {
    uint32_t a;
    asm("{ .reg .u64 t; cvta.to.shared.u64 t, %1; cvt.u32.u64 %0, t; }" : "=r"(a) : "l"(p));
    return a;
}

__device__ __forceinline__ void hl_pair(float v, __nv_bfloat16& h, __nv_bfloat16& l) {
    h = __float2bfloat16_rn(v);
    l = __float2bfloat16_rn(v - __bfloat162float(h));
}

template <int ISF16>
__device__ __forceinline__ void mma_any(float* c, uint32_t a0, uint32_t a1, uint32_t a2,
                                        uint32_t a3, uint32_t b0, uint32_t b1) {
    if (ISF16) {
        asm volatile(
            "mma.sync.aligned.m16n8k16.row.col.f32.f16.f16.f32 "
            "{%0,%1,%2,%3}, {%4,%5,%6,%7}, {%8,%9}, {%0,%1,%2,%3};\n"
            : "+f"(c[0]), "+f"(c[1]), "+f"(c[2]), "+f"(c[3])
            : "r"(a0), "r"(a1), "r"(a2), "r"(a3), "r"(b0), "r"(b1));
    } else {
        asm volatile(
            "mma.sync.aligned.m16n8k16.row.col.f32.bf16.bf16.f32 "
            "{%0,%1,%2,%3}, {%4,%5,%6,%7}, {%8,%9}, {%0,%1,%2,%3};\n"
            : "+f"(c[0]), "+f"(c[1]), "+f"(c[2]), "+f"(c[3])
            : "r"(a0), "r"(a1), "r"(a2), "r"(a3), "r"(b0), "r"(b1));
    }
}

#define LDSM_X4(r0, r1, r2, r3, addr) \
    asm volatile("ldmatrix.sync.aligned.m8n8.x4.shared.b16 {%0,%1,%2,%3}, [%4];" \
                 : "=r"(r0), "=r"(r1), "=r"(r2), "=r"(r3) : "r"(addr))

// ---------------- cubic B-spline bases --------------------------------------------
__device__ __forceinline__ void bspline8(float v, float* out) {
    float b[11];
#pragma unroll
    for (int t = 0; t < 11; t++) {
        float g0 = 0.4f * (t - 3) - 1.0f;
        float g1 = 0.4f * (t - 2) - 1.0f;
        b[t] = (v >= g0 && v < g1) ? 1.0f : 0.0f;
    }
#pragma unroll
    for (int j = 1; j <= 3; j++) {
        float inv = 1.0f / (0.4f * (float)j);
#pragma unroll
        for (int t = 0; t < 10; t++) {
            if (t < 11 - j) {
                float gt   = 0.4f * (t - 3) - 1.0f;
                float gtj1 = 0.4f * (t + j - 2) - 1.0f;
                b[t] = (v - gt) * inv * b[t] + (gtj1 - v) * inv * b[t + 1];
            }
        }
    }
#pragma unroll
    for (int c = 0; c < 8; c++) out[c] = b[c];
}

// ---------------- weight conversion kernels ----------------------------------------
__global__ void conv_kan_w_h1(const float* __restrict__ base, const float* __restrict__ spline,
                              const float* __restrict__ scaler, int Kin,
                              __half* __restrict__ W) {
    int o = blockIdx.x;
    int KA = Kin * 9;
    const float* brow = base + (size_t)o * Kin;
    const float* srow = spline + (size_t)o * Kin * 8;
    const float* crow = scaler + (size_t)o * Kin;
    __half* row = W + (size_t)o * KA;
    for (int c = threadIdx.x; c < Kin; c += 256)
        row[c] = __float2half_rn(brow[c]);
    for (int c = threadIdx.x; c < Kin * 8; c += 256)
        row[Kin + c] = __float2half_rn(srow[c] * crow[c >> 3]);
}

__global__ void conv_plain(const float* __restrict__ W,
                           __nv_bfloat16* __restrict__ WH, __nv_bfloat16* __restrict__ WL,
                           int total) {
    int i = blockIdx.x * 256 + threadIdx.x;
    if (i < total) {
        __nv_bfloat16 h, l;
        hl_pair(W[i], h, l);
        WH[i] = h; WL[i] = l;
    }
}

// ---------------- rmsnorm + phi (single fp16) + optional gate logits ---------------
__global__ void rmsnorm_phi_kernel(const float* __restrict__ x,
                                   const float* __restrict__ w,
                                   __half* __restrict__ phiF,
                                   const float* __restrict__ gate_w,
                                   float* __restrict__ logits) {
    int m = blockIdx.x;
    int tid = threadIdx.x;
    __shared__ float sx[HID];
    __shared__ float sred[256];
    const float* xr = x + (size_t)m * HID;
    float ss = 0.f;
    for (int f = tid; f < HID; f += 256) { float v = xr[f]; sx[f] = v; ss += v * v; }
    sred[tid] = ss; __syncthreads();
    for (int o = 128; o > 0; o >>= 1) { if (tid < o) sred[tid] += sred[tid + o]; __syncthreads(); }
    float rms = rsqrtf(sred[0] / (float)HID + 1e-6f);
    float gacc[4] = {0.f, 0.f, 0.f, 0.f};
    __half* ph = phiF + (size_t)m * KAUG;
    for (int f = tid; f < HID; f += 256) {
        float hn = sx[f] * rms * w[f];
        ph[f] = __float2half_rn(hn / (1.0f + expf(-hn)));
        float bs[8];
        bspline8(hn, bs);
#pragma unroll
        for (int c = 0; c < 8; c++)
            ph[HID + f * 8 + c] = __float2half_rn(bs[c]);
        if (gate_w) {
#pragma unroll
            for (int e = 0; e < 4; e++) gacc[e] += hn * gate_w[e * HID + f];
        }
    }
    if (gate_w) {
#pragma unroll
        for (int e = 0; e < 4; e++) {
            __syncthreads();
            sred[tid] = gacc[e]; __syncthreads();
            for (int o = 128; o > 0; o >>= 1) { if (tid < o) sred[tid] += sred[tid + o]; __syncthreads(); }
            if (tid == 0) logits[m * 4 + e] = sred[0];
        }
    }
}

// ---------------- phi expansion of t1*t2, batched over experts (single fp16) -------
__global__ void mul_phi_kernel() {
    int e = blockIdx.y;
    int r = blockIdx.x;
    if (r >= g_cnt[e]) return;
    int tid = threadIdx.x;
    const float* a = g_t1 + (size_t)e * TOK * DFF + (size_t)r * DFF;
    const float* b = g_t2 + (size_t)e * TOK * DFF + (size_t)r * DFF;
    __half* ph = g_phitF + (size_t)e * TOK * KAUG + (size_t)r * KAUG;
    for (int f = tid; f < DFF; f += 256) {
        float v = a[f] * b[f];
        ph[f] = __float2half_rn(v / (1.0f + expf(-v)));
        float bs[8];
        bspline8(v, bs);
#pragma unroll
        for (int c = 0; c < 8; c++)
            ph[DFF + f * 8 + c] = __float2half_rn(bs[c]);
    }
}

// ---------------- tensor-core GEMM body --------------------------------------------
// PASSES=3: tiles AH AL BH BL bf16 hi/lo split (precision anchor).
// PASSES=1: tiles A B fp16 single pass.
// EPI 0: plain fp32. EPI 1: +res+bias dual store. EPI 3: atomic scatter.
// EPI 4: RoPE then fp16 store (C reinterpreted as __half*).
#define PITCH  80
#define TILEB  (128 * PITCH)
#define GM_DYN3 (512 + 2 * 4 * TILEB)
#define GM_DYN1 (512 + 2 * 2 * TILEB)

template <int EPI, int PASSES, int ISF16>
__device__ __forceinline__ void gemm_body(
    const uint16_t* __restrict__ AH, const uint16_t* __restrict__ AL,
    int lda, const int* __restrict__ a_idx,
    const uint16_t* __restrict__ BH, const uint16_t* __restrict__ BL, int ldb,
    float* __restrict__ C, int ldc, int M, int K,
    const int* __restrict__ cnt,
    const float* __restrict__ aux0, const float* __restrict__ aux1, float* __restrict__ C2,
    const int* __restrict__ out_idx, const float* __restrict__ out_wt) {
    const int NT = (PASSES == 3) ? 4 : 2;
    const int BT = (PASSES == 3) ? 2 : 1;            // B tile index
    const uint32_t STAGEB = (uint32_t)NT * TILEB;

    int Meff = cnt ? *cnt : M;
    int mBase = blockIdx.y * 128;
    int nBase = blockIdx.x * 128;
    if (mBase >= Meff) return;

    extern __shared__ char sm[];
    int* rowmap = (int*)sm;
    uint32_t bufs_u = smem_u32(sm + 512);
    int tid = threadIdx.x;

    if (tid < 128) {
        int r = mBase + tid;
        int g = (r < Meff) ? r : mBase;
        rowmap[tid] = a_idx ? a_idx[g] : g;
    }
    __syncthreads();

    int w = tid >> 5, l = tid & 31;
    int wm = (w >> 2) * 64;
    int wn = (w & 3) * 32;
    int lq = l >> 2, lr = l & 3;
    uint32_t aOff = (uint32_t)(wm + (l & 15)) * PITCH + ((l >> 4) ? 16u : 0u);
    uint32_t bOff = (uint32_t)(wn + (l & 7) + ((l & 16) ? 8 : 0)) * PITCH + ((l & 8) ? 16u : 0u);

    float acc[4][4][4];
#pragma unroll
    for (int mf = 0; mf < 4; mf++)
#pragma unroll
        for (int nf = 0; nf < 4; nf++)
#pragma unroll
            for (int t = 0; t < 4; t++) acc[mf][nf][t] = 0.f;

    auto issue = [&](int s, int k0) {
#pragma unroll
        for (int it = 0; it < 2 * NT; it++) {
            int i = it * 256 + tid;
            int tens = i >> 9;
            int rem = i & 511;
            int row = rem >> 2;
            int seg = rem & 3;
            const uint16_t* src;
            if (PASSES == 1) {
                src = (tens == 0) ? AH + (size_t)rowmap[row] * lda + k0 + 8 * seg
                                  : BH + (size_t)(nBase + row) * ldb + k0 + 8 * seg;
            } else {
                if (tens == 0)      src = AH + (size_t)rowmap[row] * lda + k0 + 8 * seg;
                else if (tens == 1) src = AL + (size_t)rowmap[row] * lda + k0 + 8 * seg;
                else if (tens == 2) src = BH + (size_t)(nBase + row) * ldb + k0 + 8 * seg;
                else                src = BL + (size_t)(nBase + row) * ldb + k0 + 8 * seg;
            }
            uint32_t dst = bufs_u + (uint32_t)s * STAGEB + (uint32_t)tens * TILEB +
                           (uint32_t)row * PITCH + (uint32_t)seg * 16;
            asm volatile("cp.async.cg.shared.global [%0], [%1], 16;" :: "r"(dst), "l"(src) : "memory");
        }
        asm volatile("cp.async.commit_group;" ::: "memory");
    };

    int nStages = K / 32;
    issue(0, 0);
    for (int ck = 0; ck < nStages; ck++) {
        if (ck) __syncthreads();
        bool pre = (ck + 1 < nStages);
        if (pre) issue((ck + 1) & 1, (ck + 1) * 32);
        if (pre) asm volatile("cp.async.wait_group 1;" ::: "memory");
        else     asm volatile("cp.async.wait_group 0;" ::: "memory");
        __syncthreads();

        uint32_t base = bufs_u + (uint32_t)(ck & 1) * STAGEB;
#pragma unroll
        for (int p = 0; p < 2; p++) {
            uint32_t koff = 32u * p;
            if (PASSES == 3) {
                uint32_t bH[4][2], bL[4][2], af[4][4];
#pragma unroll
                for (int nh = 0; nh < 2; nh++) {
                    uint32_t r0, r1, r2, r3;
                    LDSM_X4(r0, r1, r2, r3, base + 2 * TILEB + bOff + nh * 16 * PITCH + koff);
                    bH[2 * nh][0] = r0; bH[2 * nh][1] = r1; bH[2 * nh + 1][0] = r2; bH[2 * nh + 1][1] = r3;
                    LDSM_X4(r0, r1, r2, r3, base + 3 * TILEB + bOff + nh * 16 * PITCH + koff);
                    bL[2 * nh][0] = r0; bL[2 * nh][1] = r1; bL[2 * nh + 1][0] = r2; bL[2 * nh + 1][1] = r3;
                }
#pragma unroll
                for (int mf = 0; mf < 4; mf++)
                    LDSM_X4(af[mf][0], af[mf][1], af[mf][2], af[mf][3],
                            base + 0 * TILEB + aOff + mf * 16 * PITCH + koff);
#pragma unroll
                for (int mf = 0; mf < 4; mf++)
#pragma unroll
                    for (int nf = 0; nf < 4; nf++)
                        mma_any<ISF16>(acc[mf][nf], af[mf][0], af[mf][1], af[mf][2], af[mf][3],
                                       bH[nf][0], bH[nf][1]);
#pragma unroll
                for (int mf = 0; mf < 4; mf++)
#pragma unroll
                    for (int nf = 0; nf < 4; nf++)
                        mma_any<ISF16>(acc[mf][nf], af[mf][0], af[mf][1], af[mf][2], af[mf][3],
                                       bL[nf][0], bL[nf][1]);
#pragma unroll
                for (int mf = 0; mf < 4; mf++)
                    LDSM_X4(af[mf][0], af[mf][1], af[mf][2], af[mf][3],
                            base + 1 * TILEB + aOff + mf * 16 * PITCH + koff);
#pragma unroll
                for (int mf = 0; mf < 4; mf++)
#pragma unroll
                    for (int nf = 0; nf < 4; nf++)
                        mma_any<ISF16>(acc[mf][nf], af[mf][0], af[mf][1], af[mf][2], af[mf][3],
                                       bH[nf][0], bH[nf][1]);
            } else {
                uint32_t bb[4][2], af[4][4];
#pragma unroll
                for (int nh = 0; nh < 2; nh++) {
                    uint32_t r0, r1, r2, r3;
                    LDSM_X4(r0, r1, r2, r3, base + BT * TILEB + bOff + nh * 16 * PITCH + koff);
                    bb[2 * nh][0] = r0; bb[2 * nh][1] = r1; bb[2 * nh + 1][0] = r2; bb[2 * nh + 1][1] = r3;
                }
#pragma unroll
                for (int mf = 0; mf < 4; mf++)
                    LDSM_X4(af[mf][0], af[mf][1], af[mf][2], af[mf][3],
                            base + 0 * TILEB + aOff + mf * 16 * PITCH + koff);
#pragma unroll
                for (int mf = 0; mf < 4; mf++)
#pragma unroll
                    for (int nf = 0; nf < 4; nf++)
                        mma_any<ISF16>(acc[mf][nf], af[mf][0], af[mf][1], af[mf][2], af[mf][3],
                                       bb[nf][0], bb[nf][1]);
            }
        }
    }

    // ---- epilogue ----
#pragma unroll
    for (int mf = 0; mf < 4; mf++) {
#pragma unroll
        for (int nf = 0; nf < 4; nf++) {
            float* c = acc[mf][nf];
            int r0 = mBase + wm + mf * 16 + lq;
            int c0 = nBase + wn + nf * 8 + 2 * lr;
#pragma unroll
            for (int half = 0; half < 2; half++) {
                int r = r0 + half * 8;
                if (r >= Meff) continue;
                float v0 = c[half * 2 + 0], v1 = c[half * 2 + 1];
                if (EPI == 0) {
                    C[(size_t)r * ldc + c0] = v0;
                    C[(size_t)r * ldc + c0 + 1] = v1;
                } else if (EPI == 1) {
                    float o0 = v0 + aux0[(size_t)r * ldc + c0] + aux1[c0];
                    float o1 = v1 + aux0[(size_t)r * ldc + c0 + 1] + aux1[c0 + 1];
                    C[(size_t)r * ldc + c0] = o0;  C2[(size_t)r * ldc + c0] = o0;
                    C[(size_t)r * ldc + c0 + 1] = o1; C2[(size_t)r * ldc + c0 + 1] = o1;
                } else if (EPI == 3) {
                    int tok = out_idx[r];
                    float wgt = out_wt[r];
                    atomicAdd(&C[(size_t)tok * ldc + c0], wgt * v0);
                    atomicAdd(&C[(size_t)tok * ldc + c0 + 1], wgt * v1);
                } else {   // EPI == 4: RoPE on q,k pairs then fp16 store
                    __half* Ch = (__half*)C;
                    int s = r & (SEQ - 1);
                    int sub = c0 % 192;
                    float o0, o1;
                    if (sub < 128) {
                        int d2 = (sub & 63) >> 1;
                        float cc = aux0[s * 32 + d2], sn = aux1[s * 32 + d2];
                        o0 = v0 * cc - v1 * sn;
                        o1 = v0 * sn + v1 * cc;
                    } else {
                        o0 = v0; o1 = v1;
                    }
                    *(__half2*)(Ch + (size_t)r * ldc + c0) = __floats2half2_rn(o0, o1);
                }
            }
        }
    }
}

// QKV: fp16 1-pass + fused RoPE, fp16 output
__global__ void __launch_bounds__(256, 2)
kan_gemm_qkv(const float* __restrict__ rc, const float* __restrict__ rs) {
    gemm_body<4, 1, 1>((const uint16_t*)g_phiF, nullptr, KAUG, nullptr,
                       (const uint16_t*)g_qkvwF, nullptr, KAUG,
                       (float*)g_qkvF, 3072, TOK, KAUG, nullptr, rc, rs, nullptr,
                       nullptr, nullptr);
}

// out-proj: bf16 3-pass, residual+bias dual store (precision anchor)
__global__ void __launch_bounds__(256, 2)
kan_gemm_op(const float* __restrict__ x, const float* __restrict__ bias,
            float* __restrict__ x2, float* __restrict__ out) {
    gemm_body<1, 3, 0>((const uint16_t*)g_ctxH, (const uint16_t*)g_ctxL, HID, nullptr,
                       (const uint16_t*)g_owH, (const uint16_t*)g_owL, HID,
                       x2, HID, TOK, HID, nullptr, x, bias, out, nullptr, nullptr);
}

// batched w1+w2: fp16 1-pass
__global__ void __launch_bounds__(256, 2)
kan_gemm_w12() {
    int z = blockIdx.z, e = z >> 1, sel = z & 1;
    const uint16_t* B = (const uint16_t*)((sel ? g_w2F : g_w1F) + (size_t)e * DFF * KAUG);
    float* C = (sel ? g_t2 : g_t1) + (size_t)e * TOK * DFF;
    gemm_body<0, 1, 1>((const uint16_t*)g_phiF, nullptr, KAUG,
                       g_eidx + e * TOK, B, nullptr, KAUG,
                       C, DFF, TOK, KAUG, g_cnt + e, nullptr, nullptr, nullptr, nullptr, nullptr);
}

// batched w3: fp16 1-pass, atomic scatter
__global__ void __launch_bounds__(256, 2)
kan_gemm_w3(float* __restrict__ out) {
    int e = blockIdx.z;
    gemm_body<3, 1, 1>((const uint16_t*)(g_phitF + (size_t)e * TOK * KAUG), nullptr,
                       KAUG, nullptr,
                       (const uint16_t*)(g_w3F + (size_t)e * HID * KAUG), nullptr, KAUG,
                       out, HID, TOK, KAUG, g_cnt + e, nullptr, nullptr, nullptr,
                       g_eidx + e * TOK, g_ew + e * TOK);
}

// ---------------- FlashAttention-2 on tensor cores (fp16 qkv input) ----------------
#define FAQ   128
#define FAP   72
__global__ void __launch_bounds__(256, 1)
flash_attn_kernel(const __half* __restrict__ qkv,
                  __nv_bfloat16* __restrict__ ctxH,
                  __nv_bfloat16* __restrict__ ctxL) {
    __shared__ __half Qs[FAQ * FAP];
    __shared__ __half Ks[64 * FAP];
    __shared__ __half Vs[64 * FAP];

    int qt = blockIdx.x, bh = blockIdx.y;
    int b = bh >> 4, h = bh & 15;
    int tid = threadIdx.x;
    int w = tid >> 5, l = tid & 31;
    int lq = l >> 2, lr = l & 3;
    uint32_t qs_u = smem_u32(Qs), ks_u = smem_u32(Ks), vs_u = smem_u32(Vs);

    // ---- load Q tile (pure fp16 copy) ----
    {
        int row = tid >> 1;
        int cb = (tid & 1) * 32;
        const uint4* src = (const uint4*)(qkv + (size_t)(b * SEQ + qt * FAQ + row) * 3072 +
                                          h * 192 + cb);
        uint4* dst = (uint4*)(Qs + row * FAP + cb);
#pragma unroll
        for (int u = 0; u < 4; u++) dst[u] = src[u];
    }

    float o[8][4];
#pragma unroll
    for (int t = 0; t < 8; t++)
#pragma unroll
        for (int j = 0; j < 4; j++) o[t][j] = 0.f;
    float m0 = -1e30f, m1 = -1e30f, l0 = 0.f, l1 = 0.f;

    for (int kt = 0; kt < SEQ / 64; kt++) {
        __syncthreads();
        {
            int row = tid >> 2;
            int cb = (tid & 3) * 16;
            const __half* ks = qkv + (size_t)(b * SEQ + kt * 64 + row) * 3072 + h * 192 + 64 + cb;
            const __half* vsp = ks + 64;
            uint4* kd = (uint4*)(Ks + row * FAP + cb);
            kd[0] = *(const uint4*)(ks);
            kd[1] = *(const uint4*)(ks + 8);
            uint4 vv0 = *(const uint4*)(vsp);
            uint4 vv1 = *(const uint4*)(vsp + 8);
            const __half* vh0 = (const __half*)&vv0;
            const __half* vh1 = (const __half*)&vv1;
#pragma unroll
            for (int j = 0; j < 8; j++) {
                Vs[(cb + j) * FAP + row] = vh0[j];
                Vs[(cb + 8 + j) * FAP + row] = vh1[j];
            }
        }
        __syncthreads();

        // ---- S = Q K^T ----
        float s[8][4];
#pragma unroll
        for (int t = 0; t < 8; t++)
#pragma unroll
            for (int j = 0; j < 4; j++) s[t][j] = 0.f;
#pragma unroll
        for (int kk = 0; kk < 4; kk++) {
            uint32_t a0, a1, a2, a3;
            LDSM_X4(a0, a1, a2, a3,
                    qs_u + ((w * 16 + (l & 15)) * FAP + (l >> 4) * 8 + kk * 16) * 2);
#pragma unroll
            for (int jp = 0; jp < 4; jp++) {
                uint32_t r0, r1, r2, r3;
                LDSM_X4(r0, r1, r2, r3,
                        ks_u + ((jp * 16 + (l & 7) + ((l & 16) ? 8 : 0)) * FAP + kk * 16) * 2 +
                        ((l & 8) ? 16u : 0u));
                mma_any<1>(s[2 * jp],     a0, a1, a2, a3, r0, r1);
                mma_any<1>(s[2 * jp + 1], a0, a1, a2, a3, r2, r3);
            }
        }

        // ---- softmax update ----
        float mx0 = m0, mx1 = m1;
#pragma unroll
        for (int t = 0; t < 8; t++) {
#pragma unroll
            for (int j = 0; j < 4; j++) s[t][j] *= 0.125f;
            mx0 = fmaxf(mx0, fmaxf(s[t][0], s[t][1]));
            mx1 = fmaxf(mx1, fmaxf(s[t][2], s[t][3]));
        }
        mx0 = fmaxf(mx0, __shfl_xor_sync(0xffffffff, mx0, 1));
        mx0 = fmaxf(mx0, __shfl_xor_sync(0xffffffff, mx0, 2));
        mx1 = fmaxf(mx1, __shfl_xor_sync(0xffffffff, mx1, 1));
        mx1 = fmaxf(mx1, __shfl_xor_sync(0xffffffff, mx1, 2));
        float corr0 = __expf(m0 - mx0), corr1 = __expf(m1 - mx1);
        m0 = mx0; m1 = mx1;

        uint32_t ph[8], pl[8];
        float sum0 = 0.f, sum1 = 0.f;
#pragma unroll
        for (int t = 0; t < 8; t++) {
            float p0 = __expf(s[t][0] - mx0);
            float p1 = __expf(s[t][1] - mx0);
            float p2 = __expf(s[t][2] - mx1);
            float p3 = __expf(s[t][3] - mx1);
            sum0 += p0 + p1; sum1 += p2 + p3;
            __half2 h0 = __floats2half2_rn(p0, p1);
            __half2 h1 = __floats2half2_rn(p2, p3);
            ph[t] = *reinterpret_cast<uint32_t*>(&h0);
            pl[t] = *reinterpret_cast<uint32_t*>(&h1);
        }
        sum0 += __shfl_xor_sync(0xffffffff, sum0, 1);
        sum0 += __shfl_xor_sync(0xffffffff, sum0, 2);
        sum1 += __shfl_xor_sync(0xffffffff, sum1, 1);
        sum1 += __shfl_xor_sync(0xffffffff, sum1, 2);
        l0 = corr0 * l0 + sum0;
        l1 = corr1 * l1 + sum1;
#pragma unroll
        for (int t = 0; t < 8; t++) {
            o[t][0] *= corr0; o[t][1] *= corr0;
            o[t][2] *= corr1; o[t][3] *= corr1;
        }

        // ---- O += P V ----
#pragma unroll
        for (int kk = 0; kk < 4; kk++) {
            uint32_t a0 = ph[2 * kk], a1 = pl[2 * kk];
            uint32_t a2 = ph[2 * kk + 1], a3 = pl[2 * kk + 1];
#pragma unroll
            for (int jp = 0; jp < 4; jp++) {
                uint32_t r0, r1, r2, r3;
                LDSM_X4(r0, r1, r2, r3,
                        vs_u + ((jp * 16 + (l & 7) + ((l & 16) ? 8 : 0)) * FAP + kk * 16) * 2 +
                        ((l & 8) ? 16u : 0u));
                mma_any<1>(o[2 * jp],     a0, a1, a2, a3, r0, r1);
                mma_any<1>(o[2 * jp + 1], a0, a1, a2, a3, r2, r3);
            }
        }
    }

    // ---- normalize + store ctx as bf16 hi/lo ----
    float inv0 = 1.0f / l0, inv1 = 1.0f / l1;
    int r0g = b * SEQ + qt * FAQ + w * 16 + lq;
#pragma unroll
    for (int t = 0; t < 8; t++) {
        int col = h * 64 + t * 8 + 2 * lr;
        __nv_bfloat16 hh, ll;
        size_t off0 = (size_t)r0g * HID + col;
        size_t off1 = (size_t)(r0g + 8) * HID + col;
        hl_pair(o[t][0] * inv0, hh, ll); ctxH[off0] = hh;     ctxL[off0] = ll;
        hl_pair(o[t][1] * inv0, hh, ll); ctxH[off0 + 1] = hh; ctxL[off0 + 1] = ll;
        hl_pair(o[t][2] * inv1, hh, ll); ctxH[off1] = hh;     ctxL[off1] = ll;
        hl_pair(o[t][3] * inv1, hh, ll); ctxH[off1 + 1] = hh; ctxL[off1 + 1] = ll;
    }
}

// ---------------- MoE routing -----------------------------------------------------
__global__ void init_cnt_kernel() {
    if (threadIdx.x < NEXP) g_cnt[threadIdx.x] = 0;
}

__global__ void routing_kernel() {
    int m = blockIdx.x * 256 + threadIdx.x;
    if (m >= TOK) return;
    float l[4];
#pragma unroll
    for (int e = 0; e < 4; e++) l[e] = g_logits[m * 4 + e];
    int i0 = 0; float b0 = l[0];
#pragma unroll
    for (int e = 1; e < 4; e++) if (l[e] > b0) { b0 = l[e]; i0 = e; }
    int i1 = -1; float b1 = -1e30f;
#pragma unroll
    for (int e = 0; e < 4; e++) if (e != i0 && l[e] > b1) { b1 = l[e]; i1 = e; }
    float t = expf(b1 - b0);
    float w0 = 1.0f / (1.0f + t);
    float w1 = t / (1.0f + t);
    int p0 = atomicAdd(&g_cnt[i0], 1);
    g_eidx[i0 * TOK + p0] = m; g_ew[i0 * TOK + p0] = w0;
    int p1 = atomicAdd(&g_cnt[i1], 1);
    g_eidx[i1 * TOK + p1] = m; g_ew[i1 * TOK + p1] = w1;
}

// ---------------- host orchestration ----------------------------------------------
extern "C" void kernel_launch(void* const* d_in, const int* in_sizes, int n_in,
                              void* d_out, int out_size) {
    const float* x          = (const float*)d_in[0];
    const float* rot_cos    = (const float*)d_in[1];
    const float* rot_sin    = (const float*)d_in[2];
    const float* norm1_w    = (const float*)d_in[3];
    const float* norm2_w    = (const float*)d_in[4];
    const float* qkv_base   = (const float*)d_in[5];
    const float* qkv_spline = (const float*)d_in[6];
    const float* qkv_scaler = (const float*)d_in[7];
    const float* out_w      = (const float*)d_in[8];
    const float* out_b      = (const float*)d_in[9];
    const float* gate_w     = (const float*)d_in[10];
    const float* w1_base    = (const float*)d_in[11];
    const float* w1_spline  = (const float*)d_in[12];
    const float* w1_scaler  = (const float*)d_in[13];
    const float* w2_base    = (const float*)d_in[14];
    const float* w2_spline  = (const float*)d_in[15];
    const float* w2_scaler  = (const float*)d_in[16];
    const float* w3_base    = (const float*)d_in[17];
    const float* w3_spline  = (const float*)d_in[18];
    const float* w3_scaler  = (const float*)d_in[19];
    float* out = (float*)d_out;

    __half *phiF, *qwF, *w1F, *w2F, *w3F, *qkvF;
    __nv_bfloat16 *ctxH, *ctxL, *owH, *owL;
    float *x2, *logits;
    cudaGetSymbolAddress((void**)&phiF, g_phiF);
    cudaGetSymbolAddress((void**)&qkvF, g_qkvF);
    cudaGetSymbolAddress((void**)&ctxH, g_ctxH);   cudaGetSymbolAddress((void**)&ctxL, g_ctxL);
    cudaGetSymbolAddress((void**)&qwF, g_qkvwF);
    cudaGetSymbolAddress((void**)&w1F, g_w1F);     cudaGetSymbolAddress((void**)&w2F, g_w2F);
    cudaGetSymbolAddress((void**)&w3F, g_w3F);
    cudaGetSymbolAddress((void**)&owH, g_owH);     cudaGetSymbolAddress((void**)&owL, g_owL);
    cudaGetSymbolAddress((void**)&x2, g_x2);
    cudaGetSymbolAddress((void**)&logits, g_logits);

    cudaFuncSetAttribute(kan_gemm_qkv, cudaFuncAttributeMaxDynamicSharedMemorySize, GM_DYN1);
    cudaFuncSetAttribute(kan_gemm_op,  cudaFuncAttributeMaxDynamicSharedMemorySize, GM_DYN3);
    cudaFuncSetAttribute(kan_gemm_w12, cudaFuncAttributeMaxDynamicSharedMemorySize, GM_DYN1);
    cudaFuncSetAttribute(kan_gemm_w3,  cudaFuncAttributeMaxDynamicSharedMemorySize, GM_DYN1);

    // 0) weight conversion (single fp16 except out_w)
    conv_kan_w_h1<<<3072, 256>>>(qkv_base, qkv_spline, qkv_scaler, HID, qwF);
    conv_kan_w_h1<<<NEXP * DFF, 256>>>(w1_base, w1_spline, w1_scaler, HID, w1F);
    conv_kan_w_h1<<<NEXP * DFF, 256>>>(w2_base, w2_spline, w2_scaler, HID, w2F);
    conv_kan_w_h1<<<NEXP * HID, 256>>>(w3_base, w3_spline, w3_scaler, DFF, w3F);
    conv_plain<<<(HID * HID + 255) / 256, 256>>>(out_w, owH, owL, HID * HID);

    // 1) rmsnorm(x) -> phi fp16
    rmsnorm_phi_kernel<<<TOK, 256>>>(x, norm1_w, phiF, nullptr, nullptr);

    // 2) QKV = phi @ Waug^T with fused RoPE (1-pass fp16, fp16 out)
    kan_gemm_qkv<<<dim3(3072 / 128, TOK / 128), 256, GM_DYN1>>>(rot_cos, rot_sin);

    // 3) attention (FA2 on tensor cores, fp16 in)
    flash_attn_kernel<<<dim3(SEQ / FAQ, BATCH * NHEAD), 256>>>(qkvF, ctxH, ctxL);

    // 4) x2 = x + ctx @ out_w^T + out_b (dual store into d_out)
    kan_gemm_op<<<dim3(HID / 128, TOK / 128), 256, GM_DYN3>>>(x, out_b, x2, out);

    // 5) rmsnorm(x2) -> phi fp16, gate logits
    rmsnorm_phi_kernel<<<TOK, 256>>>(x2, norm2_w, phiF, gate_w, logits);

    // 6) routing
    init_cnt_kernel<<<1, 32>>>();
    routing_kernel<<<TOK / 256, 256>>>();

    // 7) MoE batched
    kan_gemm_w12<<<dim3(DFF / 128, TOK / 128, 2 * NEXP), 256, GM_DYN1>>>();
    mul_phi_kernel<<<dim3(TOK, NEXP), 256>>>();
    kan_gemm_w3<<<dim3(HID / 128, TOK / 128, NEXP), 256, GM_DYN1>>>(out);
}

// round 16
// speedup vs baseline: 1.7601x; 1.0213x over previous
#include <cuda_runtime.h>
#include <cuda_bf16.h>
#include <cuda_fp16.h>
#include <math.h>
#include <stdint.h>

#define TOK   2048      // B*S
#define HID   1024
#define KAUG  9216      // H*(1+NB)
#define NB    8
#define NHEAD 16
#define HDIM  64
#define SEQ   1024
#define BATCH 2
#define DFF   1024
#define NEXP  4

// ---------------- scratch (static device globals; no runtime alloc) ----------------
__device__ __align__(16) __half g_phiF[(size_t)TOK * KAUG];          // single fp16
__device__ __align__(16) __half g_phitF[(size_t)NEXP * TOK * KAUG];  // single fp16
__device__ __align__(16) __half g_ctxF[(size_t)TOK * HID];           // single fp16
__device__ __align__(16) __half g_qkvwF[(size_t)3072 * KAUG];
__device__ __align__(16) __half g_w1F[(size_t)NEXP * DFF * KAUG];
__device__ __align__(16) __half g_w2F[(size_t)NEXP * DFF * KAUG];
__device__ __align__(16) __half g_w3F[(size_t)NEXP * HID * KAUG];
__device__ __align__(16) __half g_owF[(size_t)HID * HID];
__device__ __align__(16) __half g_qkvF[(size_t)TOK * 3 * HID];

__device__ float g_x2[(size_t)TOK * HID];
__device__ float g_t1[(size_t)NEXP * TOK * DFF];
__device__ float g_t2[(size_t)NEXP * TOK * DFF];
__device__ float g_logits[TOK * NEXP];
__device__ int   g_cnt[NEXP];
__device__ int   g_eidx[NEXP * TOK];
__device__ float g_ew[NEXP * TOK];

// ---------------- helpers ----------------------------------------------------------
__device__ __forceinline__ uint32_t smem_u32(const void* p) {
    uint32_t a;
    asm("{ .reg .u64 t; cvta.to.shared.u64 t, %1; cvt.u32.u64 %0, t; }" : "=r"(a) : "l"(p));
    return a;
}

template <int ISF16>
__device__ __forceinline__ void mma_any(float* c, uint32_t a0, uint32_t a1, uint32_t a2,
                                        uint32_t a3, uint32_t b0, uint32_t b1) {
    if (ISF16) {
        asm volatile(
            "mma.sync.aligned.m16n8k16.row.col.f32.f16.f16.f32 "
            "{%0,%1,%2,%3}, {%4,%5,%6,%7}, {%8,%9}, {%0,%1,%2,%3};\n"
            : "+f"(c[0]), "+f"(c[1]), "+f"(c[2]), "+f"(c[3])
            : "r"(a0), "r"(a1), "r"(a2), "r"(a3), "r"(b0), "r"(b1));
    } else {
        asm volatile(
            "mma.sync.aligned.m16n8k16.row.col.f32.bf16.bf16.f32 "
            "{%0,%1,%2,%3}, {%4,%5,%6,%7}, {%8,%9}, {%0,%1,%2,%3};\n"
            : "+f"(c[0]), "+f"(c[1]), "+f"(c[2]), "+f"(c[3])
            : "r"(a0), "r"(a1), "r"(a2), "r"(a3), "r"(b0), "r"(b1));
    }
}

#define LDSM_X4(r0, r1, r2, r3, addr) \
    asm volatile("ldmatrix.sync.aligned.m8n8.x4.shared.b16 {%0,%1,%2,%3}, [%4];" \
                 : "=r"(r0), "=r"(r1), "=r"(r2), "=r"(r3) : "r"(addr))

// ---------------- cubic B-spline bases --------------------------------------------
__device__ __forceinline__ void bspline8(float v, float* out) {
    float b[11];
#pragma unroll
    for (int t = 0; t < 11; t++) {
        float g0 = 0.4f * (t - 3) - 1.0f;
        float g1 = 0.4f * (t - 2) - 1.0f;
        b[t] = (v >= g0 && v < g1) ? 1.0f : 0.0f;
    }
#pragma unroll
    for (int j = 1; j <= 3; j++) {
        float inv = 1.0f / (0.4f * (float)j);
#pragma unroll
        for (int t = 0; t < 10; t++) {
            if (t < 11 - j) {
                float gt   = 0.4f * (t - 3) - 1.0f;
                float gtj1 = 0.4f * (t + j - 2) - 1.0f;
                b[t] = (v - gt) * inv * b[t] + (gtj1 - v) * inv * b[t + 1];
            }
        }
    }
#pragma unroll
    for (int c = 0; c < 8; c++) out[c] = b[c];
}

// ---------------- weight conversion kernels ----------------------------------------
__global__ void conv_kan_w_h1(const float* __restrict__ base, const float* __restrict__ spline,
                              const float* __restrict__ scaler, int Kin,
                              __half* __restrict__ W) {
    int o = blockIdx.x;
    int KA = Kin * 9;
    const float* brow = base + (size_t)o * Kin;
    const float* srow = spline + (size_t)o * Kin * 8;
    const float* crow = scaler + (size_t)o * Kin;
    __half* row = W + (size_t)o * KA;
    for (int c = threadIdx.x; c < Kin; c += 256)
        row[c] = __float2half_rn(brow[c]);
    for (int c = threadIdx.x; c < Kin * 8; c += 256)
        row[Kin + c] = __float2half_rn(srow[c] * crow[c >> 3]);
}

__global__ void conv_plain_h(const float* __restrict__ W, __half* __restrict__ WF, int total) {
    int i = blockIdx.x * 256 + threadIdx.x;
    if (i < total) WF[i] = __float2half_rn(W[i]);
}

// ---------------- rmsnorm + phi (single fp16) + optional gate logits ---------------
__global__ void rmsnorm_phi_kernel(const float* __restrict__ x,
                                   const float* __restrict__ w,
                                   __half* __restrict__ phiF,
                                   const float* __restrict__ gate_w,
                                   float* __restrict__ logits) {
    int m = blockIdx.x;
    int tid = threadIdx.x;
    __shared__ float sx[HID];
    __shared__ float sred[256];
    const float* xr = x + (size_t)m * HID;
    float ss = 0.f;
    for (int f = tid; f < HID; f += 256) { float v = xr[f]; sx[f] = v; ss += v * v; }
    sred[tid] = ss; __syncthreads();
    for (int o = 128; o > 0; o >>= 1) { if (tid < o) sred[tid] += sred[tid + o]; __syncthreads(); }
    float rms = rsqrtf(sred[0] / (float)HID + 1e-6f);
    float gacc[4] = {0.f, 0.f, 0.f, 0.f};
    __half* ph = phiF + (size_t)m * KAUG;
    for (int f = tid; f < HID; f += 256) {
        float hn = sx[f] * rms * w[f];
        ph[f] = __float2half_rn(hn / (1.0f + expf(-hn)));
        float bs[8];
        bspline8(hn, bs);
#pragma unroll
        for (int c = 0; c < 8; c++)
            ph[HID + f * 8 + c] = __float2half_rn(bs[c]);
        if (gate_w) {
#pragma unroll
            for (int e = 0; e < 4; e++) gacc[e] += hn * gate_w[e * HID + f];
        }
    }
    if (gate_w) {
#pragma unroll
        for (int e = 0; e < 4; e++) {
            __syncthreads();
            sred[tid] = gacc[e]; __syncthreads();
            for (int o = 128; o > 0; o >>= 1) { if (tid < o) sred[tid] += sred[tid + o]; __syncthreads(); }
            if (tid == 0) logits[m * 4 + e] = sred[0];
        }
    }
}

// ---------------- phi expansion of t1*t2, batched over experts (single fp16) -------
__global__ void mul_phi_kernel() {
    int e = blockIdx.y;
    int r = blockIdx.x;
    if (r >= g_cnt[e]) return;
    int tid = threadIdx.x;
    const float* a = g_t1 + (size_t)e * TOK * DFF + (size_t)r * DFF;
    const float* b = g_t2 + (size_t)e * TOK * DFF + (size_t)r * DFF;
    __half* ph = g_phitF + (size_t)e * TOK * KAUG + (size_t)r * KAUG;
    for (int f = tid; f < DFF; f += 256) {
        float v = a[f] * b[f];
        ph[f] = __float2half_rn(v / (1.0f + expf(-v)));
        float bs[8];
        bspline8(v, bs);
#pragma unroll
        for (int c = 0; c < 8; c++)
            ph[DFF + f * 8 + c] = __float2half_rn(bs[c]);
    }
}

// ---------------- tensor-core GEMM body --------------------------------------------
// PASSES=1: tiles A B fp16 single pass.
// EPI 0: plain fp32. EPI 1: +res+bias dual store. EPI 3: atomic scatter.
// EPI 4: RoPE then fp16 store (C reinterpreted as __half*).
#define PITCH  80
#define TILEB  (128 * PITCH)
#define GM_DYN1 (512 + 2 * 2 * TILEB)

template <int EPI, int PASSES, int ISF16>
__device__ __forceinline__ void gemm_body(
    const uint16_t* __restrict__ AH, const uint16_t* __restrict__ AL,
    int lda, const int* __restrict__ a_idx,
    const uint16_t* __restrict__ BH, const uint16_t* __restrict__ BL, int ldb,
    float* __restrict__ C, int ldc, int M, int K,
    const int* __restrict__ cnt,
    const float* __restrict__ aux0, const float* __restrict__ aux1, float* __restrict__ C2,
    const int* __restrict__ out_idx, const float* __restrict__ out_wt) {
    const int NT = (PASSES == 3) ? 4 : 2;
    const int BT = (PASSES == 3) ? 2 : 1;
    const uint32_t STAGEB = (uint32_t)NT * TILEB;

    int Meff = cnt ? *cnt : M;
    int mBase = blockIdx.y * 128;
    int nBase = blockIdx.x * 128;
    if (mBase >= Meff) return;

    extern __shared__ char sm[];
    int* rowmap = (int*)sm;
    uint32_t bufs_u = smem_u32(sm + 512);
    int tid = threadIdx.x;

    if (tid < 128) {
        int r = mBase + tid;
        int g = (r < Meff) ? r : mBase;
        rowmap[tid] = a_idx ? a_idx[g] : g;
    }
    __syncthreads();

    int w = tid >> 5, l = tid & 31;
    int wm = (w >> 2) * 64;
    int wn = (w & 3) * 32;
    int lq = l >> 2, lr = l & 3;
    uint32_t aOff = (uint32_t)(wm + (l & 15)) * PITCH + ((l >> 4) ? 16u : 0u);
    uint32_t bOff = (uint32_t)(wn + (l & 7) + ((l & 16) ? 8 : 0)) * PITCH + ((l & 8) ? 16u : 0u);

    float acc[4][4][4];
#pragma unroll
    for (int mf = 0; mf < 4; mf++)
#pragma unroll
        for (int nf = 0; nf < 4; nf++)
#pragma unroll
            for (int t = 0; t < 4; t++) acc[mf][nf][t] = 0.f;

    auto issue = [&](int s, int k0) {
#pragma unroll
        for (int it = 0; it < 2 * NT; it++) {
            int i = it * 256 + tid;
            int tens = i >> 9;
            int rem = i & 511;
            int row = rem >> 2;
            int seg = rem & 3;
            const uint16_t* src;
            if (PASSES == 1) {
                src = (tens == 0) ? AH + (size_t)rowmap[row] * lda + k0 + 8 * seg
                                  : BH + (size_t)(nBase + row) * ldb + k0 + 8 * seg;
            } else {
                if (tens == 0)      src = AH + (size_t)rowmap[row] * lda + k0 + 8 * seg;
                else if (tens == 1) src = AL + (size_t)rowmap[row] * lda + k0 + 8 * seg;
                else if (tens == 2) src = BH + (size_t)(nBase + row) * ldb + k0 + 8 * seg;
                else                src = BL + (size_t)(nBase + row) * ldb + k0 + 8 * seg;
            }
            uint32_t dst = bufs_u + (uint32_t)s * STAGEB + (uint32_t)tens * TILEB +
                           (uint32_t)row * PITCH + (uint32_t)seg * 16;
            asm volatile("cp.async.cg.shared.global [%0], [%1], 16;" :: "r"(dst), "l"(src) : "memory");
        }
        asm volatile("cp.async.commit_group;" ::: "memory");
    };

    int nStages = K / 32;
    issue(0, 0);
    for (int ck = 0; ck < nStages; ck++) {
        if (ck) __syncthreads();
        bool pre = (ck + 1 < nStages);
        if (pre) issue((ck + 1) & 1, (ck + 1) * 32);
        if (pre) asm volatile("cp.async.wait_group 1;" ::: "memory");
        else     asm volatile("cp.async.wait_group 0;" ::: "memory");
        __syncthreads();

        uint32_t base = bufs_u + (uint32_t)(ck & 1) * STAGEB;
#pragma unroll
        for (int p = 0; p < 2; p++) {
            uint32_t koff = 32u * p;
            uint32_t bb[4][2], af[4][4];
#pragma unroll
            for (int nh = 0; nh < 2; nh++) {
                uint32_t r0, r1, r2, r3;
                LDSM_X4(r0, r1, r2, r3, base + BT * TILEB + bOff + nh * 16 * PITCH + koff);
                bb[2 * nh][0] = r0; bb[2 * nh][1] = r1; bb[2 * nh + 1][0] = r2; bb[2 * nh + 1][1] = r3;
            }
#pragma unroll
            for (int mf = 0; mf < 4; mf++)
                LDSM_X4(af[mf][0], af[mf][1], af[mf][2], af[mf][3],
                        base + 0 * TILEB + aOff + mf * 16 * PITCH + koff);
#pragma unroll
            for (int mf = 0; mf < 4; mf++)
#pragma unroll
                for (int nf = 0; nf < 4; nf++)
                    mma_any<ISF16>(acc[mf][nf], af[mf][0], af[mf][1], af[mf][2], af[mf][3],
                                   bb[nf][0], bb[nf][1]);
        }
    }

    // ---- epilogue ----
#pragma unroll
    for (int mf = 0; mf < 4; mf++) {
#pragma unroll
        for (int nf = 0; nf < 4; nf++) {
            float* c = acc[mf][nf];
            int r0 = mBase + wm + mf * 16 + lq;
            int c0 = nBase + wn + nf * 8 + 2 * lr;
#pragma unroll
            for (int half = 0; half < 2; half++) {
                int r = r0 + half * 8;
                if (r >= Meff) continue;
                float v0 = c[half * 2 + 0], v1 = c[half * 2 + 1];
                if (EPI == 0) {
                    C[(size_t)r * ldc + c0] = v0;
                    C[(size_t)r * ldc + c0 + 1] = v1;
                } else if (EPI == 1) {
                    float o0 = v0 + aux0[(size_t)r * ldc + c0] + aux1[c0];
                    float o1 = v1 + aux0[(size_t)r * ldc + c0 + 1] + aux1[c0 + 1];
                    C[(size_t)r * ldc + c0] = o0;  C2[(size_t)r * ldc + c0] = o0;
                    C[(size_t)r * ldc + c0 + 1] = o1; C2[(size_t)r * ldc + c0 + 1] = o1;
                } else if (EPI == 3) {
                    int tok = out_idx[r];
                    float wgt = out_wt[r];
                    atomicAdd(&C[(size_t)tok * ldc + c0], wgt * v0);
                    atomicAdd(&C[(size_t)tok * ldc + c0 + 1], wgt * v1);
                } else {   // EPI == 4: RoPE on q,k pairs then fp16 store
                    __half* Ch = (__half*)C;
                    int s = r & (SEQ - 1);
                    int sub = c0 % 192;
                    float o0, o1;
                    if (sub < 128) {
                        int d2 = (sub & 63) >> 1;
                        float cc = aux0[s * 32 + d2], sn = aux1[s * 32 + d2];
                        o0 = v0 * cc - v1 * sn;
                        o1 = v0 * sn + v1 * cc;
                    } else {
                        o0 = v0; o1 = v1;
                    }
                    *(__half2*)(Ch + (size_t)r * ldc + c0) = __floats2half2_rn(o0, o1);
                }
            }
        }
    }
}

// QKV: fp16 1-pass + fused RoPE, fp16 output
__global__ void __launch_bounds__(256, 2)
kan_gemm_qkv(const float* __restrict__ rc, const float* __restrict__ rs) {
    gemm_body<4, 1, 1>((const uint16_t*)g_phiF, nullptr, KAUG, nullptr,
                       (const uint16_t*)g_qkvwF, nullptr, KAUG,
                       (float*)g_qkvF, 3072, TOK, KAUG, nullptr, rc, rs, nullptr,
                       nullptr, nullptr);
}

// out-proj: fp16 1-pass, residual+bias dual store
__global__ void __launch_bounds__(256, 2)
kan_gemm_op(const float* __restrict__ x, const float* __restrict__ bias,
            float* __restrict__ x2, float* __restrict__ out) {
    gemm_body<1, 1, 1>((const uint16_t*)g_ctxF, nullptr, HID, nullptr,
                       (const uint16_t*)g_owF, nullptr, HID,
                       x2, HID, TOK, HID, nullptr, x, bias, out, nullptr, nullptr);
}

// batched w1+w2: fp16 1-pass
__global__ void __launch_bounds__(256, 2)
kan_gemm_w12() {
    int z = blockIdx.z, e = z >> 1, sel = z & 1;
    const uint16_t* B = (const uint16_t*)((sel ? g_w2F : g_w1F) + (size_t)e * DFF * KAUG);
    float* C = (sel ? g_t2 : g_t1) + (size_t)e * TOK * DFF;
    gemm_body<0, 1, 1>((const uint16_t*)g_phiF, nullptr, KAUG,
                       g_eidx + e * TOK, B, nullptr, KAUG,
                       C, DFF, TOK, KAUG, g_cnt + e, nullptr, nullptr, nullptr, nullptr, nullptr);
}

// batched w3: fp16 1-pass, atomic scatter
__global__ void __launch_bounds__(256, 2)
kan_gemm_w3(float* __restrict__ out) {
    int e = blockIdx.z;
    gemm_body<3, 1, 1>((const uint16_t*)(g_phitF + (size_t)e * TOK * KAUG), nullptr,
                       KAUG, nullptr,
                       (const uint16_t*)(g_w3F + (size_t)e * HID * KAUG), nullptr, KAUG,
                       out, HID, TOK, KAUG, g_cnt + e, nullptr, nullptr, nullptr,
                       g_eidx + e * TOK, g_ew + e * TOK);
}

// ---------------- FlashAttention-2 on tensor cores (fp16 qkv input) ----------------
#define FAQ   128
#define FAP   72
__global__ void __launch_bounds__(256, 1)
flash_attn_kernel(const __half* __restrict__ qkv, __half* __restrict__ ctxF) {
    __shared__ __half Qs[FAQ * FAP];
    __shared__ __half Ks[64 * FAP];
    __shared__ __half Vs[64 * FAP];

    int qt = blockIdx.x, bh = blockIdx.y;
    int b = bh >> 4, h = bh & 15;
    int tid = threadIdx.x;
    int w = tid >> 5, l = tid & 31;
    int lq = l >> 2, lr = l & 3;
    uint32_t qs_u = smem_u32(Qs), ks_u = smem_u32(Ks), vs_u = smem_u32(Vs);

    // ---- load Q tile (pure fp16 copy) ----
    {
        int row = tid >> 1;
        int cb = (tid & 1) * 32;
        const uint4* src = (const uint4*)(qkv + (size_t)(b * SEQ + qt * FAQ + row) * 3072 +
                                          h * 192 + cb);
        uint4* dst = (uint4*)(Qs + row * FAP + cb);
#pragma unroll
        for (int u = 0; u < 4; u++) dst[u] = src[u];
    }

    float o[8][4];
#pragma unroll
    for (int t = 0; t < 8; t++)
#pragma unroll
        for (int j = 0; j < 4; j++) o[t][j] = 0.f;
    float m0 = -1e30f, m1 = -1e30f, l0 = 0.f, l1 = 0.f;

    for (int kt = 0; kt < SEQ / 64; kt++) {
        __syncthreads();
        {
            int row = tid >> 2;
            int cb = (tid & 3) * 16;
            const __half* ks = qkv + (size_t)(b * SEQ + kt * 64 + row) * 3072 + h * 192 + 64 + cb;
            const __half* vsp = ks + 64;
            uint4* kd = (uint4*)(Ks + row * FAP + cb);
            kd[0] = *(const uint4*)(ks);
            kd[1] = *(const uint4*)(ks + 8);
            uint4 vv0 = *(const uint4*)(vsp);
            uint4 vv1 = *(const uint4*)(vsp + 8);
            const __half* vh0 = (const __half*)&vv0;
            const __half* vh1 = (const __half*)&vv1;
#pragma unroll
            for (int j = 0; j < 8; j++) {
                Vs[(cb + j) * FAP + row] = vh0[j];
                Vs[(cb + 8 + j) * FAP + row] = vh1[j];
            }
        }
        __syncthreads();

        // ---- S = Q K^T ----
        float s[8][4];
#pragma unroll
        for (int t = 0; t < 8; t++)
#pragma unroll
            for (int j = 0; j < 4; j++) s[t][j] = 0.f;
#pragma unroll
        for (int kk = 0; kk < 4; kk++) {
            uint32_t a0, a1, a2, a3;
            LDSM_X4(a0, a1, a2, a3,
                    qs_u + ((w * 16 + (l & 15)) * FAP + (l >> 4) * 8 + kk * 16) * 2);
#pragma unroll
            for (int jp = 0; jp < 4; jp++) {
                uint32_t r0, r1, r2, r3;
                LDSM_X4(r0, r1, r2, r3,
                        ks_u + ((jp * 16 + (l & 7) + ((l & 16) ? 8 : 0)) * FAP + kk * 16) * 2 +
                        ((l & 8) ? 16u : 0u));
                mma_any<1>(s[2 * jp],     a0, a1, a2, a3, r0, r1);
                mma_any<1>(s[2 * jp + 1], a0, a1, a2, a3, r2, r3);
            }
        }

        // ---- softmax update ----
        float mx0 = m0, mx1 = m1;
#pragma unroll
        for (int t = 0; t < 8; t++) {
#pragma unroll
            for (int j = 0; j < 4; j++) s[t][j] *= 0.125f;
            mx0 = fmaxf(mx0, fmaxf(s[t][0], s[t][1]));
            mx1 = fmaxf(mx1, fmaxf(s[t][2], s[t][3]));
        }
        mx0 = fmaxf(mx0, __shfl_xor_sync(0xffffffff, mx0, 1));
        mx0 = fmaxf(mx0, __shfl_xor_sync(0xffffffff, mx0, 2));
        mx1 = fmaxf(mx1, __shfl_xor_sync(0xffffffff, mx1, 1));
        mx1 = fmaxf(mx1, __shfl_xor_sync(0xffffffff, mx1, 2));
        float corr0 = __expf(m0 - mx0), corr1 = __expf(m1 - mx1);
        m0 = mx0; m1 = mx1;

        uint32_t ph[8], pl[8];
        float sum0 = 0.f, sum1 = 0.f;
#pragma unroll
        for (int t = 0; t < 8; t++) {
            float p0 = __expf(s[t][0] - mx0);
            float p1 = __expf(s[t][1] - mx0);
            float p2 = __expf(s[t][2] - mx1);
            float p3 = __expf(s[t][3] - mx1);
            sum0 += p0 + p1; sum1 += p2 + p3;
            __half2 h0 = __floats2half2_rn(p0, p1);
            __half2 h1 = __floats2half2_rn(p2, p3);
            ph[t] = *reinterpret_cast<uint32_t*>(&h0);
            pl[t] = *reinterpret_cast<uint32_t*>(&h1);
        }
        sum0 += __shfl_xor_sync(0xffffffff, sum0, 1);
        sum0 += __shfl_xor_sync(0xffffffff, sum0, 2);
        sum1 += __shfl_xor_sync(0xffffffff, sum1, 1);
        sum1 += __shfl_xor_sync(0xffffffff, sum1, 2);
        l0 = corr0 * l0 + sum0;
        l1 = corr1 * l1 + sum1;
#pragma unroll
        for (int t = 0; t < 8; t++) {
            o[t][0] *= corr0; o[t][1] *= corr0;
            o[t][2] *= corr1; o[t][3] *= corr1;
        }

        // ---- O += P V ----
#pragma unroll
        for (int kk = 0; kk < 4; kk++) {
            uint32_t a0 = ph[2 * kk], a1 = pl[2 * kk];
            uint32_t a2 = ph[2 * kk + 1], a3 = pl[2 * kk + 1];
#pragma unroll
            for (int jp = 0; jp < 4; jp++) {
                uint32_t r0, r1, r2, r3;
                LDSM_X4(r0, r1, r2, r3,
                        vs_u + ((jp * 16 + (l & 7) + ((l & 16) ? 8 : 0)) * FAP + kk * 16) * 2 +
                        ((l & 8) ? 16u : 0u));
                mma_any<1>(o[2 * jp],     a0, a1, a2, a3, r0, r1);
                mma_any<1>(o[2 * jp + 1], a0, a1, a2, a3, r2, r3);
            }
        }
    }

    // ---- normalize + store ctx as fp16 ----
    float inv0 = 1.0f / l0, inv1 = 1.0f / l1;
    int r0g = b * SEQ + qt * FAQ + w * 16 + lq;
#pragma unroll
    for (int t = 0; t < 8; t++) {
        int col = h * 64 + t * 8 + 2 * lr;
        size_t off0 = (size_t)r0g * HID + col;
        size_t off1 = (size_t)(r0g + 8) * HID + col;
        *(__half2*)(ctxF + off0) = __floats2half2_rn(o[t][0] * inv0, o[t][1] * inv0);
        *(__half2*)(ctxF + off1) = __floats2half2_rn(o[t][2] * inv1, o[t][3] * inv1);
    }
}

// ---------------- MoE routing -----------------------------------------------------
__global__ void init_cnt_kernel() {
    if (threadIdx.x < NEXP) g_cnt[threadIdx.x] = 0;
}

__global__ void routing_kernel() {
    int m = blockIdx.x * 256 + threadIdx.x;
    if (m >= TOK) return;
    float l[4];
#pragma unroll
    for (int e = 0; e < 4; e++) l[e] = g_logits[m * 4 + e];
    int i0 = 0; float b0 = l[0];
#pragma unroll
    for (int e = 1; e < 4; e++) if (l[e] > b0) { b0 = l[e]; i0 = e; }
    int i1 = -1; float b1 = -1e30f;
#pragma unroll
    for (int e = 0; e < 4; e++) if (e != i0 && l[e] > b1) { b1 = l[e]; i1 = e; }
    float t = expf(b1 - b0);
    float w0 = 1.0f / (1.0f + t);
    float w1 = t / (1.0f + t);
    int p0 = atomicAdd(&g_cnt[i0], 1);
    g_eidx[i0 * TOK + p0] = m; g_ew[i0 * TOK + p0] = w0;
    int p1 = atomicAdd(&g_cnt[i1], 1);
    g_eidx[i1 * TOK + p1] = m; g_ew[i1 * TOK + p1] = w1;
}

// ---------------- host orchestration ----------------------------------------------
extern "C" void kernel_launch(void* const* d_in, const int* in_sizes, int n_in,
                              void* d_out, int out_size) {
    const float* x          = (const float*)d_in[0];
    const float* rot_cos    = (const float*)d_in[1];
    const float* rot_sin    = (const float*)d_in[2];
    const float* norm1_w    = (const float*)d_in[3];
    const float* norm2_w    = (const float*)d_in[4];
    const float* qkv_base   = (const float*)d_in[5];
    const float* qkv_spline = (const float*)d_in[6];
    const float* qkv_scaler = (const float*)d_in[7];
    const float* out_w      = (const float*)d_in[8];
    const float* out_b      = (const float*)d_in[9];
    const float* gate_w     = (const float*)d_in[10];
    const float* w1_base    = (const float*)d_in[11];
    const float* w1_spline  = (const float*)d_in[12];
    const float* w1_scaler  = (const float*)d_in[13];
    const float* w2_base    = (const float*)d_in[14];
    const float* w2_spline  = (const float*)d_in[15];
    const float* w2_scaler  = (const float*)d_in[16];
    const float* w3_base    = (const float*)d_in[17];
    const float* w3_spline  = (const float*)d_in[18];
    const float* w3_scaler  = (const float*)d_in[19];
    float* out = (float*)d_out;

    __half *phiF, *qwF, *w1F, *w2F, *w3F, *qkvF, *ctxF, *owF;
    float *x2, *logits;
    cudaGetSymbolAddress((void**)&phiF, g_phiF);
    cudaGetSymbolAddress((void**)&qkvF, g_qkvF);
    cudaGetSymbolAddress((void**)&ctxF, g_ctxF);
    cudaGetSymbolAddress((void**)&qwF, g_qkvwF);
    cudaGetSymbolAddress((void**)&w1F, g_w1F);     cudaGetSymbolAddress((void**)&w2F, g_w2F);
    cudaGetSymbolAddress((void**)&w3F, g_w3F);
    cudaGetSymbolAddress((void**)&owF, g_owF);
    cudaGetSymbolAddress((void**)&x2, g_x2);
    cudaGetSymbolAddress((void**)&logits, g_logits);

    cudaFuncSetAttribute(kan_gemm_qkv, cudaFuncAttributeMaxDynamicSharedMemorySize, GM_DYN1);
    cudaFuncSetAttribute(kan_gemm_op,  cudaFuncAttributeMaxDynamicSharedMemorySize, GM_DYN1);
    cudaFuncSetAttribute(kan_gemm_w12, cudaFuncAttributeMaxDynamicSharedMemorySize, GM_DYN1);
    cudaFuncSetAttribute(kan_gemm_w3,  cudaFuncAttributeMaxDynamicSharedMemorySize, GM_DYN1);

    // 0) weight conversion (single fp16)
    conv_kan_w_h1<<<3072, 256>>>(qkv_base, qkv_spline, qkv_scaler, HID, qwF);
    conv_kan_w_h1<<<NEXP * DFF, 256>>>(w1_base, w1_spline, w1_scaler, HID, w1F);
    conv_kan_w_h1<<<NEXP * DFF, 256>>>(w2_base, w2_spline, w2_scaler, HID, w2F);
    conv_kan_w_h1<<<NEXP * HID, 256>>>(w3_base, w3_spline, w3_scaler, DFF, w3F);
    conv_plain_h<<<(HID * HID + 255) / 256, 256>>>(out_w, owF, HID * HID);

    // 1) rmsnorm(x) -> phi fp16
    rmsnorm_phi_kernel<<<TOK, 256>>>(x, norm1_w, phiF, nullptr, nullptr);

    // 2) QKV = phi @ Waug^T with fused RoPE (1-pass fp16, fp16 out)
    kan_gemm_qkv<<<dim3(3072 / 128, TOK / 128), 256, GM_DYN1>>>(rot_cos, rot_sin);

    // 3) attention (FA2 on tensor cores, fp16 in/out)
    flash_attn_kernel<<<dim3(SEQ / FAQ, BATCH * NHEAD), 256>>>(qkvF, ctxF);

    // 4) x2 = x + ctx @ out_w^T + out_b (dual store into d_out)
    kan_gemm_op<<<dim3(HID / 128, TOK / 128), 256, GM_DYN1>>>(x, out_b, x2, out);

    // 5) rmsnorm(x2) -> phi fp16, gate logits
    rmsnorm_phi_kernel<<<TOK, 256>>>(x2, norm2_w, phiF, gate_w, logits);

    // 6) routing
    init_cnt_kernel<<<1, 32>>>();
    routing_kernel<<<TOK / 256, 256>>>();

    // 7) MoE batched
    kan_gemm_w12<<<dim3(DFF / 128, TOK / 128, 2 * NEXP), 256, GM_DYN1>>>();
    mul_phi_kernel<<<dim3(TOK, NEXP), 256>>>();
    kan_gemm_w3<<<dim3(HID / 128, TOK / 128, NEXP), 256, GM_DYN1>>>(out);
}